// round 1
// baseline (speedup 1.0000x reference)
#include <cuda_runtime.h>
#include <cuda_bf16.h>

#define BB 4
#define SS 1024
#define DD 1024
#define HH 16
#define DK 64

// Scratch (allocation-free rule: __device__ globals)
__device__ float g_q[BB * HH * SS * DK];     // [B,H,S,dk]
__device__ float g_k[BB * HH * SS * DK];
__device__ float g_v[BB * HH * SS * DK];
__device__ float g_attn[BB * SS * DD];       // [B,S,D]

// ---------------------------------------------------------------------------
// SGEMM: C = A[M,K] @ W[K,N] + bias[N]
//   mode 0: C[m*N+n]                  (plain [B,S,D] layout)
//   mode 1: C[((b*H+h)*S+s)*DK + d]   (head-split layout, b=m/S, s=m%S, h=n/64, d=n%64)
// BM=BN=128, BK=8, 256 threads, 8x8 per thread.
// ---------------------------------------------------------------------------
__global__ void __launch_bounds__(256) sgemm_bias_kernel(
    const float* __restrict__ A, const float* __restrict__ W,
    const float* __restrict__ bias, float* __restrict__ C,
    int M, int N, int K, int mode)
{
    __shared__ float As[8][128];
    __shared__ float Bs[8][128];

    const int tid = threadIdx.x;
    const int bm = blockIdx.y * 128;
    const int bn = blockIdx.x * 128;

    const int arow = tid >> 1;            // 0..127
    const int aseg = (tid & 1) * 4;       // 0 or 4
    const int brow = tid >> 5;            // 0..7
    const int bcol = (tid & 31) * 4;      // 0..124

    const int tx = tid & 15;              // 0..15
    const int ty = tid >> 4;              // 0..15

    float acc[8][8];
#pragma unroll
    for (int i = 0; i < 8; i++)
#pragma unroll
        for (int j = 0; j < 8; j++) acc[i][j] = 0.f;

    for (int k0 = 0; k0 < K; k0 += 8) {
        float4 av = *(const float4*)(A + (size_t)(bm + arow) * K + k0 + aseg);
        As[aseg + 0][arow] = av.x;
        As[aseg + 1][arow] = av.y;
        As[aseg + 2][arow] = av.z;
        As[aseg + 3][arow] = av.w;

        float4 bv = *(const float4*)(W + (size_t)(k0 + brow) * N + bn + bcol);
        *(float4*)&Bs[brow][bcol] = bv;

        __syncthreads();

#pragma unroll
        for (int kk = 0; kk < 8; kk++) {
            float ra[8], rb[8];
            *(float4*)(ra)     = *(const float4*)&As[kk][ty * 8];
            *(float4*)(ra + 4) = *(const float4*)&As[kk][ty * 8 + 4];
            *(float4*)(rb)     = *(const float4*)&Bs[kk][tx * 8];
            *(float4*)(rb + 4) = *(const float4*)&Bs[kk][tx * 8 + 4];
#pragma unroll
            for (int i = 0; i < 8; i++)
#pragma unroll
                for (int j = 0; j < 8; j++)
                    acc[i][j] = fmaf(ra[i], rb[j], acc[i][j]);
        }
        __syncthreads();
    }

    // epilogue
#pragma unroll
    for (int i = 0; i < 8; i++) {
        int m = bm + ty * 8 + i;
#pragma unroll
        for (int j = 0; j < 8; j++) {
            int n = bn + tx * 8 + j;
            float val = acc[i][j] + __ldg(bias + n);
            if (mode == 0) {
                C[(size_t)m * N + n] = val;
            } else {
                int b = m >> 10;          // m / S
                int s = m & 1023;         // m % S
                int h = n >> 6;           // n / 64
                int d = n & 63;           // n % 64
                C[(((size_t)(b * HH + h)) * SS + s) * DK + d] = val;
            }
        }
    }
}

// ---------------------------------------------------------------------------
// Sparse attention: one warp per query row.
// Row i attends to: locals j=i-1,i-2,i-3 (if >=0)  and strided j=i-4u, u=0..i/4.
// Max count = 3 + 256 = 259.
// ---------------------------------------------------------------------------
__global__ void __launch_bounds__(256) sparse_attn_kernel(
    const float* __restrict__ q, const float* __restrict__ k,
    const float* __restrict__ v, float* __restrict__ out)
{
    __shared__ float sc[8][264];

    const int warp = threadIdx.x >> 5;
    const int lane = threadIdx.x & 31;
    const int row  = blockIdx.x * 8 + warp;   // 0 .. B*H*S-1
    const int bh   = row >> 10;               // b*H + h
    const int i    = row & 1023;

    const float* qp    = q + (size_t)row * DK;
    const float* kbase = k + (size_t)bh * SS * DK;
    const float* vbase = v + (size_t)bh * SS * DK;

    float2 qv = *(const float2*)(qp + lane * 2);
    const float scale = 0.125f;               // 1/sqrt(64)
    qv.x *= scale; qv.y *= scale;

    const int nloc = min(i, 3);
    const int cnt  = nloc + (i >> 2) + 1;

    // --- scores ---
    for (int t = 0; t < cnt; t++) {
        int j = (t < nloc) ? (i - 1 - t) : (i - 4 * (t - nloc));
        const float* kp = kbase + (size_t)j * DK;
        float2 kv = *(const float2*)(kp + lane * 2);
        float p = qv.x * kv.x + qv.y * kv.y;
#pragma unroll
        for (int o = 16; o; o >>= 1) p += __shfl_xor_sync(0xffffffffu, p, o);
        if (lane == 0) sc[warp][t] = p;
    }
    __syncwarp();

    // --- softmax ---
    float mx = -1e30f;
    for (int t = lane; t < cnt; t += 32) mx = fmaxf(mx, sc[warp][t]);
#pragma unroll
    for (int o = 16; o; o >>= 1) mx = fmaxf(mx, __shfl_xor_sync(0xffffffffu, mx, o));

    float ssum = 0.f;
    for (int t = lane; t < cnt; t += 32) {
        float e = __expf(sc[warp][t] - mx);
        sc[warp][t] = e;
        ssum += e;
    }
#pragma unroll
    for (int o = 16; o; o >>= 1) ssum += __shfl_xor_sync(0xffffffffu, ssum, o);
    const float inv = 1.0f / ssum;
    __syncwarp();

    // --- P @ V ---
    float ox = 0.f, oy = 0.f;
    for (int t = 0; t < cnt; t++) {
        int j = (t < nloc) ? (i - 1 - t) : (i - 4 * (t - nloc));
        float p = sc[warp][t];
        const float* vp = vbase + (size_t)j * DK;
        float2 vv = *(const float2*)(vp + lane * 2);
        ox = fmaf(p, vv.x, ox);
        oy = fmaf(p, vv.y, oy);
    }
    ox *= inv; oy *= inv;

    // write to [B,S,D]: (b*S+i)*D + h*64 + lane*2
    const int b = bh >> 4;
    const int h = bh & 15;
    float* op = out + ((size_t)(b * SS + i)) * DD + h * DK + lane * 2;
    *(float2*)op = make_float2(ox, oy);
}

// ---------------------------------------------------------------------------
extern "C" void kernel_launch(void* const* d_in, const int* in_sizes, int n_in,
                              void* d_out, int out_size)
{
    const float* Q  = (const float*)d_in[0];
    const float* K  = (const float*)d_in[1];
    const float* V  = (const float*)d_in[2];
    const float* Wq = (const float*)d_in[3];
    const float* bq = (const float*)d_in[4];
    const float* Wk = (const float*)d_in[5];
    const float* bk = (const float*)d_in[6];
    const float* Wv = (const float*)d_in[7];
    const float* bv = (const float*)d_in[8];
    const float* Wo = (const float*)d_in[9];
    const float* bo = (const float*)d_in[10];
    float* out = (float*)d_out;

    float *pq, *pk, *pv, *pa;
    cudaGetSymbolAddress((void**)&pq, g_q);
    cudaGetSymbolAddress((void**)&pk, g_k);
    cudaGetSymbolAddress((void**)&pv, g_v);
    cudaGetSymbolAddress((void**)&pa, g_attn);

    const int M = BB * SS;   // 4096
    const int N = DD;        // 1024
    const int Kd = DD;       // 1024

    dim3 gg(N / 128, M / 128);  // (8, 32)
    dim3 tb(256);

    sgemm_bias_kernel<<<gg, tb>>>(Q, Wq, bq, pq, M, N, Kd, 1);
    sgemm_bias_kernel<<<gg, tb>>>(K, Wk, bk, pk, M, N, Kd, 1);
    sgemm_bias_kernel<<<gg, tb>>>(V, Wv, bv, pv, M, N, Kd, 1);

    sparse_attn_kernel<<<(BB * HH * SS) / 8, 256>>>(pq, pk, pv, pa);

    sgemm_bias_kernel<<<gg, tb>>>(pa, Wo, bo, out, M, N, Kd, 0);
}

// round 2
// speedup vs baseline: 1.8607x; 1.8607x over previous
#include <cuda_runtime.h>
#include <cuda_bf16.h>
#include <cstdint>

#define BB 4
#define SS 1024
#define DD 1024
#define HH 16
#define DK 64

// Scratch (__device__ globals: allocation-free rule)
__device__ float g_q[BB * HH * SS * DK];     // [b,h,s,d]
__device__ float g_k[BB * HH * SS * DK];     // residue-permuted [bh][r][u][d]
__device__ float g_v[BB * HH * SS * DK];     // residue-permuted [bh][r][u][d]
__device__ float g_attn[BB * SS * DD];       // [B,S,D]

// ---------------------------------------------------------------------------
// PTX helpers
// ---------------------------------------------------------------------------
__device__ __forceinline__ unsigned saddr(const void* p) {
    return (unsigned)__cvta_generic_to_shared(p);
}
__device__ __forceinline__ void ldm_x4(uint32_t* r, const void* p) {
    asm volatile("ldmatrix.sync.aligned.m8n8.x4.shared.b16 {%0,%1,%2,%3}, [%4];"
        : "=r"(r[0]), "=r"(r[1]), "=r"(r[2]), "=r"(r[3]) : "r"(saddr(p)));
}
__device__ __forceinline__ void ldm_x4_t(uint32_t* r, const void* p) {
    asm volatile("ldmatrix.sync.aligned.m8n8.x4.trans.shared.b16 {%0,%1,%2,%3}, [%4];"
        : "=r"(r[0]), "=r"(r[1]), "=r"(r[2]), "=r"(r[3]) : "r"(saddr(p)));
}
__device__ __forceinline__ void mma16816(float* c, const uint32_t* a, const uint32_t* b) {
    asm volatile("mma.sync.aligned.m16n8k16.row.col.f32.bf16.bf16.f32 "
        "{%0,%1,%2,%3},{%4,%5,%6,%7},{%8,%9},{%0,%1,%2,%3};"
        : "+f"(c[0]), "+f"(c[1]), "+f"(c[2]), "+f"(c[3])
        : "r"(a[0]), "r"(a[1]), "r"(a[2]), "r"(a[3]), "r"(b[0]), "r"(b[1]));
}

// split fp32 -> bf16 hi + bf16 lo
__device__ __forceinline__ void cvt4(const float4 v, uint2& hi, uint2& lo) {
    __nv_bfloat16 h0 = __float2bfloat16(v.x), h1 = __float2bfloat16(v.y);
    __nv_bfloat16 h2 = __float2bfloat16(v.z), h3 = __float2bfloat16(v.w);
    __nv_bfloat16 l0 = __float2bfloat16(v.x - __bfloat162float(h0));
    __nv_bfloat16 l1 = __float2bfloat16(v.y - __bfloat162float(h1));
    __nv_bfloat16 l2 = __float2bfloat16(v.z - __bfloat162float(h2));
    __nv_bfloat16 l3 = __float2bfloat16(v.w - __bfloat162float(h3));
    __nv_bfloat162 ph0 = __nv_bfloat162(h0, h1), ph1 = __nv_bfloat162(h2, h3);
    __nv_bfloat162 pl0 = __nv_bfloat162(l0, l1), pl1 = __nv_bfloat162(l2, l3);
    hi.x = *(uint32_t*)&ph0; hi.y = *(uint32_t*)&ph1;
    lo.x = *(uint32_t*)&pl0; lo.y = *(uint32_t*)&pl1;
}

// ---------------------------------------------------------------------------
// Split-bf16 GEMM: C = A[4096,1024] @ W[1024,1024] + bias, tensor cores.
// mode 0: C[m*1024+n]
// mode 1: C[((b*16+h)*1024+s)*64+d]                     (q layout)
// mode 2: C[(((b*16+h)*4 + s%4)*256 + s/4)*64 + d]      (residue-permuted k/v)
// ---------------------------------------------------------------------------
__device__ __forceinline__ void store2(float* __restrict__ C, int mode,
                                       int m, int n, float v0, float v1) {
    size_t idx;
    if (mode == 0) {
        idx = (size_t)m * 1024 + n;
    } else {
        int b = m >> 10, s = m & 1023, h = n >> 6, d = n & 63;
        if (mode == 1) idx = (((size_t)(b * 16 + h)) * 1024 + s) * 64 + d;
        else           idx = ((((size_t)(b * 16 + h)) * 4 + (s & 3)) * 256 + (s >> 2)) * 64 + d;
    }
    *(float2*)(C + idx) = make_float2(v0, v1);
}

__global__ void __launch_bounds__(256, 2) gemm_split_kernel(
    const float* __restrict__ A, const float* __restrict__ W,
    const float* __restrict__ bias, float* __restrict__ C, int mode)
{
    __shared__ __nv_bfloat16 Ah[128][40], Al[128][40];   // [m][k], pad 40
    __shared__ __nv_bfloat16 Wh[32][136], Wl[32][136];   // [k][n], pad 136

    const int tid = threadIdx.x;
    const int bm = blockIdx.y * 128, bn = blockIdx.x * 128;
    const int w = tid >> 5, lane = tid & 31;
    const int wm = (w & 1) * 64;       // warp m offset
    const int wn = (w >> 1) * 32;      // warp n offset

    const int arow = tid >> 1, akseg = (tid & 1) * 16;
    const int wrow = tid >> 3, wnseg = (tid & 7) * 16;

    float acc[4][4][4];
#pragma unroll
    for (int i = 0; i < 4; i++)
#pragma unroll
        for (int j = 0; j < 4; j++)
#pragma unroll
            for (int t = 0; t < 4; t++) acc[i][j][t] = 0.f;

    const int lrow = lane & 15, lcol = (lane >> 4) << 3;

    for (int k0 = 0; k0 < 1024; k0 += 32) {
        // stage A tile (fp32 -> bf16 hi/lo)
#pragma unroll
        for (int jj = 0; jj < 4; jj++) {
            float4 v = *(const float4*)(A + (size_t)(bm + arow) * 1024 + k0 + akseg + jj * 4);
            uint2 hi, lo; cvt4(v, hi, lo);
            *(uint2*)&Ah[arow][akseg + jj * 4] = hi;
            *(uint2*)&Al[arow][akseg + jj * 4] = lo;
        }
        // stage W tile
#pragma unroll
        for (int jj = 0; jj < 4; jj++) {
            float4 v = *(const float4*)(W + (size_t)(k0 + wrow) * 1024 + bn + wnseg + jj * 4);
            uint2 hi, lo; cvt4(v, hi, lo);
            *(uint2*)&Wh[wrow][wnseg + jj * 4] = hi;
            *(uint2*)&Wl[wrow][wnseg + jj * 4] = lo;
        }
        __syncthreads();

#pragma unroll
        for (int kk = 0; kk < 32; kk += 16) {
            uint32_t a[4][4], bh_[2][4], bl_[2][4];
#pragma unroll
            for (int mt = 0; mt < 4; mt++)
                ldm_x4(a[mt], &Ah[wm + mt * 16 + lrow][kk + lcol]);
#pragma unroll
            for (int np = 0; np < 2; np++) {
                ldm_x4_t(bh_[np], &Wh[kk + lrow][wn + np * 16 + lcol]);
                ldm_x4_t(bl_[np], &Wl[kk + lrow][wn + np * 16 + lcol]);
            }
            // Ah*Wh + Ah*Wl
#pragma unroll
            for (int mt = 0; mt < 4; mt++)
#pragma unroll
                for (int nt = 0; nt < 4; nt++) {
                    mma16816(acc[mt][nt], a[mt], &bh_[nt >> 1][(nt & 1) * 2]);
                    mma16816(acc[mt][nt], a[mt], &bl_[nt >> 1][(nt & 1) * 2]);
                }
            // Al*Wh
#pragma unroll
            for (int mt = 0; mt < 4; mt++)
                ldm_x4(a[mt], &Al[wm + mt * 16 + lrow][kk + lcol]);
#pragma unroll
            for (int mt = 0; mt < 4; mt++)
#pragma unroll
                for (int nt = 0; nt < 4; nt++)
                    mma16816(acc[mt][nt], a[mt], &bh_[nt >> 1][(nt & 1) * 2]);
        }
        __syncthreads();
    }

    // epilogue
    const int g = lane >> 2, t4 = lane & 3;
#pragma unroll
    for (int mt = 0; mt < 4; mt++)
#pragma unroll
        for (int nt = 0; nt < 4; nt++) {
            int m0 = bm + wm + mt * 16 + g;
            int n0 = bn + wn + nt * 8 + t4 * 2;
            float b0 = __ldg(bias + n0), b1 = __ldg(bias + n0 + 1);
            store2(C, mode, m0,     n0, acc[mt][nt][0] + b0, acc[mt][nt][1] + b1);
            store2(C, mode, m0 + 8, n0, acc[mt][nt][2] + b0, acc[mt][nt][3] + b1);
        }
}

// ---------------------------------------------------------------------------
// Densified sparse attention over residue classes.
// Block: one (bh, r, qtile of 32 queries i = 4*(q0+qq)+r).
// Strided keys are rows u=0..i/4 of kperm[bh][r]; locals j=i-1..i-3 handled
// separately (disjoint from strided set since 1..3 % 4 != 0).
// ---------------------------------------------------------------------------
#define SSTR 261

__global__ void __launch_bounds__(256) attn_dense_kernel(
    const float* __restrict__ q, const float* __restrict__ kperm,
    const float* __restrict__ vperm, float* __restrict__ out)
{
    extern __shared__ float sm[];
    float* S    = sm;                 // [32][261]
    float* Qs   = S + 32 * SSTR;      // [32][64]
    float* Ks   = Qs + 32 * 64;       // [32][68]  (reused for V)
    float* Ssum = Ks + 32 * 68;       // [32]

    const int tid = threadIdx.x;
    const int bh = blockIdx.x >> 5;
    const int r  = (blockIdx.x >> 3) & 3;
    const int qt = blockIdx.x & 7;
    const int q0 = qt * 32;
    const int Ls = q0 + 32;           // local-scores column base
    const int ntiles = qt + 1;

    // load Q tile, scaled by 1/sqrt(64)
    {
        int qq = tid >> 3, seg = (tid & 7) * 8;
        const float* src = q + ((size_t)bh * 1024 + 4 * (q0 + qq) + r) * 64 + seg;
        float4 a = *(const float4*)src;
        float4 b = *(const float4*)(src + 4);
        a.x *= 0.125f; a.y *= 0.125f; a.z *= 0.125f; a.w *= 0.125f;
        b.x *= 0.125f; b.y *= 0.125f; b.z *= 0.125f; b.w *= 0.125f;
        *(float4*)&Qs[qq * 64 + seg] = a;
        *(float4*)&Qs[qq * 64 + seg + 4] = b;
    }
    __syncthreads();

    // local scores (j = i-1, i-2, i-3)
    if (tid < 96) {
        int qq = tid / 3, l = tid - qq * 3;
        int i = 4 * (q0 + qq) + r;
        int j = i - 1 - l;
        float s = -1e30f;
        if (j >= 0) {
            const float* kp = kperm + (((size_t)bh * 4 + (j & 3)) * 256 + (j >> 2)) * 64;
            float acc = 0.f;
#pragma unroll
            for (int d = 0; d < 64; d += 4) {
                float4 kv = *(const float4*)(kp + d);
                float4 qv = *(const float4*)&Qs[qq * 64 + d];
                acc += qv.x * kv.x + qv.y * kv.y + qv.z * kv.z + qv.w * kv.w;
            }
            s = acc;
        }
        S[qq * SSTR + Ls + l] = s;
    }

    const float* kbase = kperm + ((size_t)bh * 4 + r) * 256 * 64;
    const float* vbase = vperm + ((size_t)bh * 4 + r) * 256 * 64;
    const int lu = tid >> 3, lseg = (tid & 7) * 8;   // tile-load map
    const int su = tid & 31, sqg = tid >> 5;          // score map

    // strided score tiles
    for (int ut = 0; ut < ntiles; ut++) {
        __syncthreads();
        {
            const float* src = kbase + (size_t)(ut * 32 + lu) * 64 + lseg;
            *(float4*)&Ks[lu * 68 + lseg]     = *(const float4*)src;
            *(float4*)&Ks[lu * 68 + lseg + 4] = *(const float4*)(src + 4);
        }
        __syncthreads();

        float s0 = 0.f, s1 = 0.f, s2 = 0.f, s3 = 0.f;
#pragma unroll
        for (int d = 0; d < 64; d += 4) {
            float4 kv = *(const float4*)&Ks[su * 68 + d];
            float4 qa = *(const float4*)&Qs[(sqg * 4 + 0) * 64 + d];
            float4 qb = *(const float4*)&Qs[(sqg * 4 + 1) * 64 + d];
            float4 qc = *(const float4*)&Qs[(sqg * 4 + 2) * 64 + d];
            float4 qd = *(const float4*)&Qs[(sqg * 4 + 3) * 64 + d];
            s0 += qa.x * kv.x + qa.y * kv.y + qa.z * kv.z + qa.w * kv.w;
            s1 += qb.x * kv.x + qb.y * kv.y + qb.z * kv.z + qb.w * kv.w;
            s2 += qc.x * kv.x + qc.y * kv.y + qc.z * kv.z + qc.w * kv.w;
            s3 += qd.x * kv.x + qd.y * kv.y + qd.z * kv.z + qd.w * kv.w;
        }
        int uglob = ut * 32 + su;
        float sv[4] = {s0, s1, s2, s3};
#pragma unroll
        for (int c = 0; c < 4; c++) {
            int qloc = sqg * 4 + c;
            S[qloc * SSTR + uglob] = (uglob <= q0 + qloc) ? sv[c] : -1e30f;
        }
    }
    __syncthreads();

    // softmax (8 warps x 4 rows)
    {
        int ww = tid >> 5, lane = tid & 31;
        int limit = Ls + 3;
        for (int qq = ww * 4; qq < ww * 4 + 4; qq++) {
            float mx = -1e30f;
            for (int t = lane; t < limit; t += 32) mx = fmaxf(mx, S[qq * SSTR + t]);
#pragma unroll
            for (int o = 16; o; o >>= 1) mx = fmaxf(mx, __shfl_xor_sync(0xffffffffu, mx, o));
            float sum = 0.f;
            for (int t = lane; t < limit; t += 32) {
                float e = __expf(S[qq * SSTR + t] - mx);
                S[qq * SSTR + t] = e;
                sum += e;
            }
#pragma unroll
            for (int o = 16; o; o >>= 1) sum += __shfl_xor_sync(0xffffffffu, sum, o);
            if (lane == 0) Ssum[qq] = sum;
        }
    }

    // PV over strided tiles (V reuses Ks buffer)
    const int pq = tid >> 3, pd = (tid & 7) * 8;
    float o0 = 0.f, o1 = 0.f, o2 = 0.f, o3 = 0.f, o4 = 0.f, o5 = 0.f, o6 = 0.f, o7 = 0.f;
    for (int ut = 0; ut < ntiles; ut++) {
        __syncthreads();
        {
            const float* src = vbase + (size_t)(ut * 32 + lu) * 64 + lseg;
            *(float4*)&Ks[lu * 68 + lseg]     = *(const float4*)src;
            *(float4*)&Ks[lu * 68 + lseg + 4] = *(const float4*)(src + 4);
        }
        __syncthreads();
#pragma unroll 4
        for (int u = 0; u < 32; u++) {
            float p = S[pq * SSTR + ut * 32 + u];
            float4 v0 = *(const float4*)&Ks[u * 68 + pd];
            float4 v1 = *(const float4*)&Ks[u * 68 + pd + 4];
            o0 += p * v0.x; o1 += p * v0.y; o2 += p * v0.z; o3 += p * v0.w;
            o4 += p * v1.x; o5 += p * v1.y; o6 += p * v1.z; o7 += p * v1.w;
        }
    }

    // locals PV + write
    {
        int i = 4 * (q0 + pq) + r;
#pragma unroll
        for (int l = 0; l < 3; l++) {
            int j = i - 1 - l;
            if (j >= 0) {
                float p = S[pq * SSTR + Ls + l];
                const float* vp = vperm + (((size_t)bh * 4 + (j & 3)) * 256 + (j >> 2)) * 64 + pd;
                float4 v0 = *(const float4*)vp;
                float4 v1 = *(const float4*)(vp + 4);
                o0 += p * v0.x; o1 += p * v0.y; o2 += p * v0.z; o3 += p * v0.w;
                o4 += p * v1.x; o5 += p * v1.y; o6 += p * v1.z; o7 += p * v1.w;
            }
        }
        float inv = 1.0f / Ssum[pq];
        int b = bh >> 4, h = bh & 15;
        float* op = out + ((size_t)(b * 1024 + i)) * 1024 + h * 64 + pd;
        *(float4*)op       = make_float4(o0 * inv, o1 * inv, o2 * inv, o3 * inv);
        *(float4*)(op + 4) = make_float4(o4 * inv, o5 * inv, o6 * inv, o7 * inv);
    }
}

// ---------------------------------------------------------------------------
extern "C" void kernel_launch(void* const* d_in, const int* in_sizes, int n_in,
                              void* d_out, int out_size)
{
    const float* Q  = (const float*)d_in[0];
    const float* K  = (const float*)d_in[1];
    const float* V  = (const float*)d_in[2];
    const float* Wq = (const float*)d_in[3];
    const float* bq = (const float*)d_in[4];
    const float* Wk = (const float*)d_in[5];
    const float* bk = (const float*)d_in[6];
    const float* Wv = (const float*)d_in[7];
    const float* bv = (const float*)d_in[8];
    const float* Wo = (const float*)d_in[9];
    const float* bo = (const float*)d_in[10];
    float* out = (float*)d_out;

    float *pq, *pk, *pv, *pa;
    cudaGetSymbolAddress((void**)&pq, g_q);
    cudaGetSymbolAddress((void**)&pk, g_k);
    cudaGetSymbolAddress((void**)&pv, g_v);
    cudaGetSymbolAddress((void**)&pa, g_attn);

    static bool attr_set = false;
    if (!attr_set) {
        cudaFuncSetAttribute(attn_dense_kernel,
                             cudaFuncAttributeMaxDynamicSharedMemorySize,
                             (32 * SSTR + 32 * 64 + 32 * 68 + 32) * 4);
        attr_set = true;
    }

    dim3 gg(8, 32);   // N/128, M/128
    dim3 tb(256);

    gemm_split_kernel<<<gg, tb>>>(Q, Wq, bq, pq, 1);
    gemm_split_kernel<<<gg, tb>>>(K, Wk, bk, pk, 2);
    gemm_split_kernel<<<gg, tb>>>(V, Wv, bv, pv, 2);

    attn_dense_kernel<<<2048, 256, (32 * SSTR + 32 * 64 + 32 * 68 + 32) * 4>>>(pq, pk, pv, pa);

    gemm_split_kernel<<<gg, tb>>>(pa, Wo, bo, out, 0);
}

// round 4
// speedup vs baseline: 2.2195x; 1.1928x over previous
#include <cuda_runtime.h>
#include <cuda_bf16.h>
#include <cstdint>

#define BB 4
#define SS 1024
#define DD 1024
#define HH 16
#define DK 64
#define NEL (BB * HH * SS * DK)   // 4M

// Scratch (__device__ globals)
__device__ __nv_bfloat16 g_qh[NEL], g_ql[NEL];   // [bh][s][d]
__device__ __nv_bfloat16 g_kh[NEL], g_kl[NEL];   // [bh][r][u][d]
__device__ __nv_bfloat16 g_vh[NEL], g_vl[NEL];   // [bh][r][u][d]
__device__ float g_attn[BB * SS * DD];           // [B,S,D]

// ---------------------------------------------------------------------------
__device__ __forceinline__ unsigned saddr(const void* p) {
    return (unsigned)__cvta_generic_to_shared(p);
}
__device__ __forceinline__ void ldm_x4(uint32_t* r, const void* p) {
    asm volatile("ldmatrix.sync.aligned.m8n8.x4.shared.b16 {%0,%1,%2,%3}, [%4];"
        : "=r"(r[0]), "=r"(r[1]), "=r"(r[2]), "=r"(r[3]) : "r"(saddr(p)));
}
__device__ __forceinline__ void ldm_x4_t(uint32_t* r, const void* p) {
    asm volatile("ldmatrix.sync.aligned.m8n8.x4.trans.shared.b16 {%0,%1,%2,%3}, [%4];"
        : "=r"(r[0]), "=r"(r[1]), "=r"(r[2]), "=r"(r[3]) : "r"(saddr(p)));
}
__device__ __forceinline__ void mma16816(float* c, const uint32_t* a, const uint32_t* b) {
    asm volatile("mma.sync.aligned.m16n8k16.row.col.f32.bf16.bf16.f32 "
        "{%0,%1,%2,%3},{%4,%5,%6,%7},{%8,%9},{%0,%1,%2,%3};"
        : "+f"(c[0]), "+f"(c[1]), "+f"(c[2]), "+f"(c[3])
        : "r"(a[0]), "r"(a[1]), "r"(a[2]), "r"(a[3]), "r"(b[0]), "r"(b[1]));
}
__device__ __forceinline__ void cvt4(const float4 v, uint2& hi, uint2& lo) {
    __nv_bfloat16 h0 = __float2bfloat16(v.x), h1 = __float2bfloat16(v.y);
    __nv_bfloat16 h2 = __float2bfloat16(v.z), h3 = __float2bfloat16(v.w);
    __nv_bfloat16 l0 = __float2bfloat16(v.x - __bfloat162float(h0));
    __nv_bfloat16 l1 = __float2bfloat16(v.y - __bfloat162float(h1));
    __nv_bfloat16 l2 = __float2bfloat16(v.z - __bfloat162float(h2));
    __nv_bfloat16 l3 = __float2bfloat16(v.w - __bfloat162float(h3));
    __nv_bfloat162 ph0(h0, h1), ph1(h2, h3), pl0(l0, l1), pl1(l2, l3);
    hi.x = *(uint32_t*)&ph0; hi.y = *(uint32_t*)&ph1;
    lo.x = *(uint32_t*)&pl0; lo.y = *(uint32_t*)&pl1;
}

// ---------------------------------------------------------------------------
// Split-bf16 GEMM, double-buffered smem + register prefetch.
// mode 0: fp32 C[m*1024+n]
// mode 1: bf16 hi/lo, idx = ((b*16+h)*1024+s)*64+d             (q)
// mode 2: bf16 hi/lo, idx = (((b*16+h)*4+(s&3))*256+(s>>2))*64+d  (k/v perm)
// ---------------------------------------------------------------------------
#define A_SZ (128 * 40)
#define W_SZ (32 * 136)
#define GEMM_SMEM ((4 * A_SZ + 4 * W_SZ) * 2)

__device__ __forceinline__ void store2(
    float* __restrict__ C, __nv_bfloat16* __restrict__ Oh,
    __nv_bfloat16* __restrict__ Ol, int mode, int m, int n, float v0, float v1)
{
    if (mode == 0) {
        *(float2*)(C + (size_t)m * 1024 + n) = make_float2(v0, v1);
        return;
    }
    int b = m >> 10, s = m & 1023, h = n >> 6, d = n & 63;
    size_t idx;
    if (mode == 1) idx = (((size_t)(b * 16 + h)) * 1024 + s) * 64 + d;
    else           idx = ((((size_t)(b * 16 + h)) * 4 + (s & 3)) * 256 + (s >> 2)) * 64 + d;
    __nv_bfloat16 h0 = __float2bfloat16(v0), h1 = __float2bfloat16(v1);
    __nv_bfloat16 l0 = __float2bfloat16(v0 - __bfloat162float(h0));
    __nv_bfloat16 l1 = __float2bfloat16(v1 - __bfloat162float(h1));
    __nv_bfloat162 ph(h0, h1), pl(l0, l1);
    *(__nv_bfloat162*)(Oh + idx) = ph;
    *(__nv_bfloat162*)(Ol + idx) = pl;
}

__global__ void __launch_bounds__(256) gemm_split_kernel(
    const float* __restrict__ A, const float* __restrict__ W,
    const float* __restrict__ bias, float* __restrict__ C,
    __nv_bfloat16* __restrict__ Oh, __nv_bfloat16* __restrict__ Ol, int mode)
{
    extern __shared__ __nv_bfloat16 smem[];
    __nv_bfloat16* sAh = smem;                       // [2][128][40]
    __nv_bfloat16* sAl = smem + 2 * A_SZ;
    __nv_bfloat16* sWh = smem + 4 * A_SZ;            // [2][32][136]
    __nv_bfloat16* sWl = smem + 4 * A_SZ + 2 * W_SZ;

    const int tid = threadIdx.x;
    const int bm = blockIdx.y * 128, bn = blockIdx.x * 128;
    const int w = tid >> 5, lane = tid & 31;
    const int wm = (w & 1) * 64, wn = (w >> 1) * 32;
    const int arow = tid >> 1, akseg = (tid & 1) * 16;
    const int wrow = tid >> 3, wnseg = (tid & 7) * 16;
    const int lrow = lane & 15, lcol = (lane >> 4) << 3;

    float acc[4][4][4];
#pragma unroll
    for (int i = 0; i < 4; i++)
#pragma unroll
        for (int j = 0; j < 4; j++)
#pragma unroll
            for (int t = 0; t < 4; t++) acc[i][j][t] = 0.f;

    float4 av[4], wv[4];
#pragma unroll
    for (int jj = 0; jj < 4; jj++) {
        av[jj] = *(const float4*)(A + (size_t)(bm + arow) * 1024 + akseg + jj * 4);
        wv[jj] = *(const float4*)(W + (size_t)wrow * 1024 + bn + wnseg + jj * 4);
    }
#pragma unroll
    for (int jj = 0; jj < 4; jj++) {
        uint2 hi, lo;
        cvt4(av[jj], hi, lo);
        *(uint2*)&sAh[arow * 40 + akseg + jj * 4] = hi;
        *(uint2*)&sAl[arow * 40 + akseg + jj * 4] = lo;
        cvt4(wv[jj], hi, lo);
        *(uint2*)&sWh[wrow * 136 + wnseg + jj * 4] = hi;
        *(uint2*)&sWl[wrow * 136 + wnseg + jj * 4] = lo;
    }
    __syncthreads();

    int buf = 0;
    for (int k0 = 0; k0 < 1024; k0 += 32) {
        const bool next = (k0 + 32 < 1024);
        if (next) {
#pragma unroll
            for (int jj = 0; jj < 4; jj++) {
                av[jj] = *(const float4*)(A + (size_t)(bm + arow) * 1024 + k0 + 32 + akseg + jj * 4);
                wv[jj] = *(const float4*)(W + (size_t)(k0 + 32 + wrow) * 1024 + bn + wnseg + jj * 4);
            }
        }

        const __nv_bfloat16* cAh = sAh + buf * A_SZ;
        const __nv_bfloat16* cAl = sAl + buf * A_SZ;
        const __nv_bfloat16* cWh = sWh + buf * W_SZ;
        const __nv_bfloat16* cWl = sWl + buf * W_SZ;

#pragma unroll
        for (int kk = 0; kk < 32; kk += 16) {
            uint32_t a[4][4], bh_[2][4], bl_[2][4];
#pragma unroll
            for (int mt = 0; mt < 4; mt++)
                ldm_x4(a[mt], &cAh[(wm + mt * 16 + lrow) * 40 + kk + lcol]);
#pragma unroll
            for (int np = 0; np < 2; np++) {
                ldm_x4_t(bh_[np], &cWh[(kk + lrow) * 136 + wn + np * 16 + lcol]);
                ldm_x4_t(bl_[np], &cWl[(kk + lrow) * 136 + wn + np * 16 + lcol]);
            }
#pragma unroll
            for (int mt = 0; mt < 4; mt++)
#pragma unroll
                for (int nt = 0; nt < 4; nt++) {
                    mma16816(acc[mt][nt], a[mt], &bh_[nt >> 1][(nt & 1) * 2]);
                    mma16816(acc[mt][nt], a[mt], &bl_[nt >> 1][(nt & 1) * 2]);
                }
#pragma unroll
            for (int mt = 0; mt < 4; mt++)
                ldm_x4(a[mt], &cAl[(wm + mt * 16 + lrow) * 40 + kk + lcol]);
#pragma unroll
            for (int mt = 0; mt < 4; mt++)
#pragma unroll
                for (int nt = 0; nt < 4; nt++)
                    mma16816(acc[mt][nt], a[mt], &bh_[nt >> 1][(nt & 1) * 2]);
        }

        if (next) {
            int b2 = buf ^ 1;
#pragma unroll
            for (int jj = 0; jj < 4; jj++) {
                uint2 hi, lo;
                cvt4(av[jj], hi, lo);
                *(uint2*)&sAh[b2 * A_SZ + arow * 40 + akseg + jj * 4] = hi;
                *(uint2*)&sAl[b2 * A_SZ + arow * 40 + akseg + jj * 4] = lo;
                cvt4(wv[jj], hi, lo);
                *(uint2*)&sWh[b2 * W_SZ + wrow * 136 + wnseg + jj * 4] = hi;
                *(uint2*)&sWl[b2 * W_SZ + wrow * 136 + wnseg + jj * 4] = lo;
            }
        }
        __syncthreads();
        buf ^= 1;
    }

    const int g = lane >> 2, t4 = lane & 3;
#pragma unroll
    for (int mt = 0; mt < 4; mt++)
#pragma unroll
        for (int nt = 0; nt < 4; nt++) {
            int m0 = bm + wm + mt * 16 + g;
            int n0 = bn + wn + nt * 8 + t4 * 2;
            float b0 = __ldg(bias + n0), b1 = __ldg(bias + n0 + 1);
            store2(C, Oh, Ol, mode, m0,     n0, acc[mt][nt][0] + b0, acc[mt][nt][1] + b1);
            store2(C, Oh, Ol, mode, m0 + 8, n0, acc[mt][nt][2] + b0, acc[mt][nt][3] + b1);
        }
}

// ---------------------------------------------------------------------------
// Tensor-core sparse attention.
// Block = (bh, r, qt): 64 queries i = 4*(q0+q)+r, q0 = qt*64.
// smem layout (floats): S [64][276] = 17664 | Qb hi+lo (9216 bf16 = 4608) |
//                       Kb hi+lo (9216 bf16 = 4608) | Ssum (64)
// ---------------------------------------------------------------------------
#define SROW 276           // floats per S row (byte stride 1104)
#define QSTR 72            // bf16 per Q/K/V row
#define ATTN_SMEM ((64 * SROW + 4608 + 4608 + 64) * 4)

__global__ void __launch_bounds__(256) attn_mma_kernel(
    const __nv_bfloat16* __restrict__ qh, const __nv_bfloat16* __restrict__ ql,
    const __nv_bfloat16* __restrict__ kh, const __nv_bfloat16* __restrict__ kl,
    const __nv_bfloat16* __restrict__ vh, const __nv_bfloat16* __restrict__ vl,
    float* __restrict__ out)
{
    extern __shared__ float sm[];
    float* S = sm;                                         // [64][276]
    __nv_bfloat16* Qb = (__nv_bfloat16*)(sm + 64 * SROW);  // hi [64][72], lo at +4608 (bf16)
    __nv_bfloat16* Kb = (__nv_bfloat16*)(sm + 64 * SROW + 4608);  // hi [64][72], lo at +4608
    float* Ssum = sm + 64 * SROW + 9216;
    float* Osm  = (float*)Qb;                              // [64][68] reuse (4352 <= 4608 floats)

    const int tid = threadIdx.x, lane = tid & 31, w = tid >> 5;
    const int bh = blockIdx.x >> 4;
    const int r  = (blockIdx.x >> 2) & 3;
    const int qt = blockIdx.x & 3;
    const int q0 = qt * 64;
    const int ntiles = qt + 1;

    const int cq = tid >> 2, cd = (tid & 3) * 16;   // copy map (64 rows x 16 elems)

    // P1: load Q hi/lo
    {
        int i = 4 * (q0 + cq) + r;
        size_t g = ((size_t)bh * 1024 + i) * 64 + cd;
        *(uint4*)&Qb[cq * QSTR + cd]           = *(const uint4*)(qh + g);
        *(uint4*)&Qb[cq * QSTR + cd + 8]       = *(const uint4*)(qh + g + 8);
        *(uint4*)&Qb[4608 + cq * QSTR + cd]     = *(const uint4*)(ql + g);
        *(uint4*)&Qb[4608 + cq * QSTR + cd + 8] = *(const uint4*)(ql + g + 8);
    }
    __syncthreads();

    // P2: local scores -> S[q][268+l]
    {
        int q = tid >> 2, l = tid & 3;
        if (l < 3) {
            int i = 4 * (q0 + q) + r, j = i - 1 - l;
            float s = -1e30f;
            if (j >= 0) {
                size_t kg = (((size_t)bh * 4 + (j & 3)) * 256 + (j >> 2)) * 64;
                float acc = 0.f;
#pragma unroll
                for (int d = 0; d < 64; d += 2) {
                    __nv_bfloat162 qhv = *(const __nv_bfloat162*)&Qb[q * QSTR + d];
                    __nv_bfloat162 qlv = *(const __nv_bfloat162*)&Qb[4608 + q * QSTR + d];
                    __nv_bfloat162 khv = *(const __nv_bfloat162*)(kh + kg + d);
                    __nv_bfloat162 klv = *(const __nv_bfloat162*)(kl + kg + d);
                    float qa = __bfloat162float(qhv.x) + __bfloat162float(qlv.x);
                    float qb2 = __bfloat162float(qhv.y) + __bfloat162float(qlv.y);
                    float ka = __bfloat162float(khv.x) + __bfloat162float(klv.x);
                    float kb2 = __bfloat162float(khv.y) + __bfloat162float(klv.y);
                    acc += qa * ka + qb2 * kb2;
                }
                s = acc * 0.125f;
            }
            S[q * SROW + 268 + l] = s;
        }
    }

    // MMA maps
    const int wm = (w & 3) * 16, wn = (w >> 2) * 32;
    const int lrow = lane & 15, lcol = (lane >> 4) << 3;
    const int bnrow = ((lane >> 4) << 3) + (lane & 7);      // B non-trans row
    const int bkoff = ((lane >> 3) & 1) << 3;               // B non-trans k-off
    const int g8 = lane >> 2, t4 = lane & 3;

    // P3: score MMA over k-tiles
    for (int ut = 0; ut < ntiles; ut++) {
        __syncthreads();
        {
            size_t g = (((size_t)bh * 4 + r) * 256 + ut * 64 + cq) * 64 + cd;
            *(uint4*)&Kb[cq * QSTR + cd]           = *(const uint4*)(kh + g);
            *(uint4*)&Kb[cq * QSTR + cd + 8]       = *(const uint4*)(kh + g + 8);
            *(uint4*)&Kb[4608 + cq * QSTR + cd]     = *(const uint4*)(kl + g);
            *(uint4*)&Kb[4608 + cq * QSTR + cd + 8] = *(const uint4*)(kl + g + 8);
        }
        __syncthreads();

        float acc[4][4];
#pragma unroll
        for (int a = 0; a < 4; a++)
#pragma unroll
            for (int b = 0; b < 4; b++) acc[a][b] = 0.f;

#pragma unroll
        for (int ks = 0; ks < 4; ks++) {
            uint32_t ah[4], al[4];
            ldm_x4(ah, &Qb[(wm + lrow) * QSTR + ks * 16 + lcol]);
            ldm_x4(al, &Qb[4608 + (wm + lrow) * QSTR + ks * 16 + lcol]);
#pragma unroll
            for (int half = 0; half < 2; half++) {
                uint32_t bh4[4], bl4[4];
                ldm_x4(bh4, &Kb[(wn + half * 16 + bnrow) * QSTR + ks * 16 + bkoff]);
                ldm_x4(bl4, &Kb[4608 + (wn + half * 16 + bnrow) * QSTR + ks * 16 + bkoff]);
#pragma unroll
                for (int sub = 0; sub < 2; sub++) {
                    int nt = half * 2 + sub;
                    mma16816(acc[nt], ah, &bh4[sub * 2]);
                    mma16816(acc[nt], ah, &bl4[sub * 2]);
                    mma16816(acc[nt], al, &bh4[sub * 2]);
                }
            }
        }
        // epilogue: mask + scale -> S fp32
#pragma unroll
        for (int nt = 0; nt < 4; nt++) {
            int ug = ut * 64 + wn + nt * 8 + t4 * 2;
#pragma unroll
            for (int rr = 0; rr < 2; rr++) {
                int qloc = wm + g8 + rr * 8;
                int qg = q0 + qloc;
                S[qloc * SROW + ug]     = (ug     <= qg) ? acc[nt][rr * 2]     * 0.125f : -1e30f;
                S[qloc * SROW + ug + 1] = (ug + 1 <= qg) ? acc[nt][rr * 2 + 1] * 0.125f : -1e30f;
            }
        }
    }
    __syncthreads();

    // P4: softmax; rewrite rows in place as packed bf16 hi (bytes [0,512)) / lo ([544,1056))
    {
        const int klim = ntiles * 64;
        for (int q = w * 8; q < w * 8 + 8; q++) {
            float vals[8];
            int nv = 0;
            float mx = -1e30f;
            for (int t = lane; t < klim; t += 32) {
                float s = S[q * SROW + t];
                vals[nv++] = s;
                mx = fmaxf(mx, s);
            }
            float lv = (lane < 3) ? S[q * SROW + 268 + lane] : -1e30f;
            mx = fmaxf(mx, lv);
#pragma unroll
            for (int o = 16; o; o >>= 1) mx = fmaxf(mx, __shfl_xor_sync(0xffffffffu, mx, o));
            __syncwarp();
            __nv_bfloat16* Ph = (__nv_bfloat16*)((char*)S + (size_t)q * SROW * 4);
            float sum = 0.f;
            nv = 0;
            for (int t = lane; t < klim; t += 32) {
                float e = __expf(vals[nv++] - mx);
                sum += e;
                __nv_bfloat16 ph = __float2bfloat16(e);
                Ph[t] = ph;
                Ph[272 + t] = __float2bfloat16(e - __bfloat162float(ph));
            }
            if (lane < 3) {
                float e = __expf(lv - mx);
                sum += e;
                S[q * SROW + 268 + lane] = e;
            }
#pragma unroll
            for (int o = 16; o; o >>= 1) sum += __shfl_xor_sync(0xffffffffu, sum, o);
            if (lane == 0) Ssum[q] = sum;
        }
    }

    // P5: PV MMA (V reuses Kb)
    float oacc[4][4];
#pragma unroll
    for (int a = 0; a < 4; a++)
#pragma unroll
        for (int b = 0; b < 4; b++) oacc[a][b] = 0.f;

    for (int ut = 0; ut < ntiles; ut++) {
        __syncthreads();
        {
            size_t g = (((size_t)bh * 4 + r) * 256 + ut * 64 + cq) * 64 + cd;
            *(uint4*)&Kb[cq * QSTR + cd]           = *(const uint4*)(vh + g);
            *(uint4*)&Kb[cq * QSTR + cd + 8]       = *(const uint4*)(vh + g + 8);
            *(uint4*)&Kb[4608 + cq * QSTR + cd]     = *(const uint4*)(vl + g);
            *(uint4*)&Kb[4608 + cq * QSTR + cd + 8] = *(const uint4*)(vl + g + 8);
        }
        __syncthreads();

#pragma unroll
        for (int ks = 0; ks < 4; ks++) {
            uint32_t ph4[4], pl4[4];
            char* prow = (char*)S + (size_t)(wm + lrow) * SROW * 4;
            int kc = ut * 64 + ks * 16 + lcol;
            ldm_x4(ph4, prow + 2 * kc);
            ldm_x4(pl4, prow + 544 + 2 * kc);
#pragma unroll
            for (int half = 0; half < 2; half++) {
                uint32_t vh4[4], vl4[4];
                ldm_x4_t(vh4, &Kb[(ks * 16 + lrow) * QSTR + wn + half * 16 + lcol]);
                ldm_x4_t(vl4, &Kb[4608 + (ks * 16 + lrow) * QSTR + wn + half * 16 + lcol]);
#pragma unroll
                for (int sub = 0; sub < 2; sub++) {
                    int nt = half * 2 + sub;
                    mma16816(oacc[nt], ph4, &vh4[sub * 2]);
                    mma16816(oacc[nt], ph4, &vl4[sub * 2]);
                    mma16816(oacc[nt], pl4, &vh4[sub * 2]);
                }
            }
        }
    }
    __syncthreads();   // all Qb uses done; safe to overwrite as Osm
#pragma unroll
    for (int nt = 0; nt < 4; nt++) {
        int dcol = wn + nt * 8 + t4 * 2;
        Osm[(wm + g8) * 68 + dcol]         = oacc[nt][0];
        Osm[(wm + g8) * 68 + dcol + 1]     = oacc[nt][1];
        Osm[(wm + g8 + 8) * 68 + dcol]     = oacc[nt][2];
        Osm[(wm + g8 + 8) * 68 + dcol + 1] = oacc[nt][3];
    }
    __syncthreads();

    // P6: locals PV + normalize + write
    {
        int q = cq, dseg = cd;
        int i = 4 * (q0 + q) + r;
        float inv = 1.0f / Ssum[q];
        float o[16];
#pragma unroll
        for (int d = 0; d < 16; d++) o[d] = Osm[q * 68 + dseg + d];
#pragma unroll
        for (int l = 0; l < 3; l++) {
            int j = i - 1 - l;
            if (j >= 0) {
                float p = S[q * SROW + 268 + l];
                size_t vg = (((size_t)bh * 4 + (j & 3)) * 256 + (j >> 2)) * 64 + dseg;
#pragma unroll
                for (int d = 0; d < 16; d += 2) {
                    __nv_bfloat162 a = *(const __nv_bfloat162*)(vh + vg + d);
                    __nv_bfloat162 b = *(const __nv_bfloat162*)(vl + vg + d);
                    o[d]     += p * (__bfloat162float(a.x) + __bfloat162float(b.x));
                    o[d + 1] += p * (__bfloat162float(a.y) + __bfloat162float(b.y));
                }
            }
        }
        int bb = bh >> 4, h = bh & 15;
        float* op = out + ((size_t)(bb * 1024 + i)) * 1024 + h * 64 + dseg;
#pragma unroll
        for (int d = 0; d < 16; d += 4)
            *(float4*)(op + d) = make_float4(o[d] * inv, o[d + 1] * inv, o[d + 2] * inv, o[d + 3] * inv);
    }
}

// ---------------------------------------------------------------------------
extern "C" void kernel_launch(void* const* d_in, const int* in_sizes, int n_in,
                              void* d_out, int out_size)
{
    const float* Q  = (const float*)d_in[0];
    const float* K  = (const float*)d_in[1];
    const float* V  = (const float*)d_in[2];
    const float* Wq = (const float*)d_in[3];
    const float* bq = (const float*)d_in[4];
    const float* Wk = (const float*)d_in[5];
    const float* bk = (const float*)d_in[6];
    const float* Wv = (const float*)d_in[7];
    const float* bv = (const float*)d_in[8];
    const float* Wo = (const float*)d_in[9];
    const float* bo = (const float*)d_in[10];
    float* out = (float*)d_out;

    __nv_bfloat16 *pqh, *pql, *pkh, *pkl, *pvh, *pvl;
    float* pa;
    cudaGetSymbolAddress((void**)&pqh, g_qh);
    cudaGetSymbolAddress((void**)&pql, g_ql);
    cudaGetSymbolAddress((void**)&pkh, g_kh);
    cudaGetSymbolAddress((void**)&pkl, g_kl);
    cudaGetSymbolAddress((void**)&pvh, g_vh);
    cudaGetSymbolAddress((void**)&pvl, g_vl);
    cudaGetSymbolAddress((void**)&pa, g_attn);

    cudaFuncSetAttribute(gemm_split_kernel,
                         cudaFuncAttributeMaxDynamicSharedMemorySize, GEMM_SMEM);
    cudaFuncSetAttribute(attn_mma_kernel,
                         cudaFuncAttributeMaxDynamicSharedMemorySize, ATTN_SMEM);

    dim3 gg(8, 32);
    dim3 tb(256);

    gemm_split_kernel<<<gg, tb, GEMM_SMEM>>>(Q, Wq, bq, nullptr, pqh, pql, 1);
    gemm_split_kernel<<<gg, tb, GEMM_SMEM>>>(K, Wk, bk, nullptr, pkh, pkl, 2);
    gemm_split_kernel<<<gg, tb, GEMM_SMEM>>>(V, Wv, bv, nullptr, pvh, pvl, 2);

    attn_mma_kernel<<<1024, 256, ATTN_SMEM>>>(pqh, pql, pkh, pkl, pvh, pvl, pa);

    gemm_split_kernel<<<gg, tb, GEMM_SMEM>>>(pa, Wo, bo, out, nullptr, nullptr, 0);
}

// round 5
// speedup vs baseline: 3.9527x; 1.7809x over previous
#include <cuda_runtime.h>
#include <cuda_fp16.h>
#include <cstdint>

#define BB 4
#define SS 1024
#define DD 1024
#define HH 16
#define DK 64
#define NEL (BB * HH * SS * DK)   // 4M

// Scratch (__device__ globals)
__device__ __half g_q[NEL];          // [bh][s][d]
__device__ __half g_k[NEL];          // [bh][r][u][d]
__device__ __half g_v[NEL];          // [bh][r][u][d]
__device__ float g_attn[BB * SS * DD];

// ---------------------------------------------------------------------------
__device__ __forceinline__ unsigned saddr(const void* p) {
    return (unsigned)__cvta_generic_to_shared(p);
}
__device__ __forceinline__ void ldm_x4(uint32_t* r, const void* p) {
    asm volatile("ldmatrix.sync.aligned.m8n8.x4.shared.b16 {%0,%1,%2,%3}, [%4];"
        : "=r"(r[0]), "=r"(r[1]), "=r"(r[2]), "=r"(r[3]) : "r"(saddr(p)));
}
__device__ __forceinline__ void ldm_x4_t(uint32_t* r, const void* p) {
    asm volatile("ldmatrix.sync.aligned.m8n8.x4.trans.shared.b16 {%0,%1,%2,%3}, [%4];"
        : "=r"(r[0]), "=r"(r[1]), "=r"(r[2]), "=r"(r[3]) : "r"(saddr(p)));
}
__device__ __forceinline__ void mma16816(float* c, const uint32_t* a, const uint32_t* b) {
    asm volatile("mma.sync.aligned.m16n8k16.row.col.f32.f16.f16.f32 "
        "{%0,%1,%2,%3},{%4,%5,%6,%7},{%8,%9},{%0,%1,%2,%3};"
        : "+f"(c[0]), "+f"(c[1]), "+f"(c[2]), "+f"(c[3])
        : "r"(a[0]), "r"(a[1]), "r"(a[2]), "r"(a[3]), "r"(b[0]), "r"(b[1]));
}
__device__ __forceinline__ uint2 cvt4h(const float4 v) {
    __half2 p0 = __floats2half2_rn(v.x, v.y);
    __half2 p1 = __floats2half2_rn(v.z, v.w);
    uint2 r;
    r.x = *(uint32_t*)&p0; r.y = *(uint32_t*)&p1;
    return r;
}

// ---------------------------------------------------------------------------
// fp16 single-pass GEMM: C = A[4096,1024] @ W[1024,1024] + bias
// mode 0: fp32 C[m*1024+n]
// mode 1: fp16, idx = ((b*16+h)*1024+s)*64+d               (q)
// mode 2: fp16, idx = (((b*16+h)*4+(s&3))*256+(s>>2))*64+d (k/v perm)
// ---------------------------------------------------------------------------
#define A_SZ (128 * 40)
#define W_SZ (32 * 136)
#define GEMM_SMEM ((2 * A_SZ + 2 * W_SZ) * 2)

__device__ __forceinline__ void store2(
    float* __restrict__ C, __half* __restrict__ O, int mode,
    int m, int n, float v0, float v1)
{
    if (mode == 0) {
        *(float2*)(C + (size_t)m * 1024 + n) = make_float2(v0, v1);
        return;
    }
    int b = m >> 10, s = m & 1023, h = n >> 6, d = n & 63;
    size_t idx;
    if (mode == 1) idx = (((size_t)(b * 16 + h)) * 1024 + s) * 64 + d;
    else           idx = ((((size_t)(b * 16 + h)) * 4 + (s & 3)) * 256 + (s >> 2)) * 64 + d;
    __half2 p = __floats2half2_rn(v0, v1);
    *(__half2*)(O + idx) = p;
}

__global__ void __launch_bounds__(256) gemm_half_kernel(
    const float* __restrict__ A, const float* __restrict__ W,
    const float* __restrict__ bias, float* __restrict__ C,
    __half* __restrict__ O, int mode)
{
    extern __shared__ __half smem[];
    __half* sA = smem;                 // [2][128][40]
    __half* sW = smem + 2 * A_SZ;      // [2][32][136]

    const int tid = threadIdx.x;
    const int bm = blockIdx.y * 128, bn = blockIdx.x * 128;
    const int w = tid >> 5, lane = tid & 31;
    const int wm = (w & 1) * 64, wn = (w >> 1) * 32;
    const int arow = tid >> 1, akseg = (tid & 1) * 16;
    const int wrow = tid >> 3, wnseg = (tid & 7) * 16;
    const int lrow = lane & 15, lcol = (lane >> 4) << 3;

    float acc[4][4][4];
#pragma unroll
    for (int i = 0; i < 4; i++)
#pragma unroll
        for (int j = 0; j < 4; j++)
#pragma unroll
            for (int t = 0; t < 4; t++) acc[i][j][t] = 0.f;

    float4 av[4], wv[4];
#pragma unroll
    for (int jj = 0; jj < 4; jj++) {
        av[jj] = *(const float4*)(A + (size_t)(bm + arow) * 1024 + akseg + jj * 4);
        wv[jj] = *(const float4*)(W + (size_t)wrow * 1024 + bn + wnseg + jj * 4);
    }
#pragma unroll
    for (int jj = 0; jj < 4; jj++) {
        *(uint2*)&sA[arow * 40 + akseg + jj * 4] = cvt4h(av[jj]);
        *(uint2*)&sW[wrow * 136 + wnseg + jj * 4] = cvt4h(wv[jj]);
    }
    __syncthreads();

    int buf = 0;
    for (int k0 = 0; k0 < 1024; k0 += 32) {
        const bool next = (k0 + 32 < 1024);
        if (next) {
#pragma unroll
            for (int jj = 0; jj < 4; jj++) {
                av[jj] = *(const float4*)(A + (size_t)(bm + arow) * 1024 + k0 + 32 + akseg + jj * 4);
                wv[jj] = *(const float4*)(W + (size_t)(k0 + 32 + wrow) * 1024 + bn + wnseg + jj * 4);
            }
        }

        const __half* cA = sA + buf * A_SZ;
        const __half* cW = sW + buf * W_SZ;

#pragma unroll
        for (int kk = 0; kk < 32; kk += 16) {
            uint32_t a[4][4], b_[2][4];
#pragma unroll
            for (int mt = 0; mt < 4; mt++)
                ldm_x4(a[mt], &cA[(wm + mt * 16 + lrow) * 40 + kk + lcol]);
#pragma unroll
            for (int np = 0; np < 2; np++)
                ldm_x4_t(b_[np], &cW[(kk + lrow) * 136 + wn + np * 16 + lcol]);
#pragma unroll
            for (int mt = 0; mt < 4; mt++)
#pragma unroll
                for (int nt = 0; nt < 4; nt++)
                    mma16816(acc[mt][nt], a[mt], &b_[nt >> 1][(nt & 1) * 2]);
        }

        if (next) {
            int b2 = buf ^ 1;
#pragma unroll
            for (int jj = 0; jj < 4; jj++) {
                *(uint2*)&sA[b2 * A_SZ + arow * 40 + akseg + jj * 4] = cvt4h(av[jj]);
                *(uint2*)&sW[b2 * W_SZ + wrow * 136 + wnseg + jj * 4] = cvt4h(wv[jj]);
            }
        }
        __syncthreads();
        buf ^= 1;
    }

    const int g = lane >> 2, t4 = lane & 3;
#pragma unroll
    for (int mt = 0; mt < 4; mt++)
#pragma unroll
        for (int nt = 0; nt < 4; nt++) {
            int m0 = bm + wm + mt * 16 + g;
            int n0 = bn + wn + nt * 8 + t4 * 2;
            float b0 = __ldg(bias + n0), b1 = __ldg(bias + n0 + 1);
            store2(C, O, mode, m0,     n0, acc[mt][nt][0] + b0, acc[mt][nt][1] + b1);
            store2(C, O, mode, m0 + 8, n0, acc[mt][nt][2] + b0, acc[mt][nt][3] + b1);
        }
}

// ---------------------------------------------------------------------------
// Tensor-core sparse attention, fp16 single-pass.
// Block = (bh, r, qt): 64 queries i = 4*(q0+q)+r.
// smem (floats): S [64][276]=17664 | Qb (2304) | Kb (2304) | Ssum (64)
// ---------------------------------------------------------------------------
#define SROW 276           // floats per S row (byte stride 1104)
#define QSTR 72            // halfs per Q/K/V row
#define ATTN_SMEM ((64 * SROW + 2304 + 2304 + 64) * 4)

__global__ void __launch_bounds__(256) attn_mma_kernel(
    const __half* __restrict__ qg, const __half* __restrict__ kg,
    const __half* __restrict__ vg, float* __restrict__ out)
{
    extern __shared__ float sm[];
    float* S = sm;                                    // [64][276]
    __half* Qb = (__half*)(sm + 64 * SROW);           // [64][72]
    __half* Kb = (__half*)(sm + 64 * SROW + 2304);    // [64][72]
    float* Ssum = sm + 64 * SROW + 4608;
    float* Osm  = (float*)Qb;                         // [64][68] spans Qb+Kb (4608 floats)

    const int tid = threadIdx.x, lane = tid & 31, w = tid >> 5;
    // heavy tiles (qt=3) first for better wave tail
    const int qt = 3 - (blockIdx.x >> 8);
    const int bh = (blockIdx.x & 255) >> 2;
    const int r  = blockIdx.x & 3;
    const int q0 = qt * 64;
    const int ntiles = qt + 1;

    const int cq = tid >> 2, cd = (tid & 3) * 16;   // copy map (64 rows x 16 halfs)

    // P1: load Q
    {
        int i = 4 * (q0 + cq) + r;
        size_t g = ((size_t)bh * 1024 + i) * 64 + cd;
        *(uint4*)&Qb[cq * QSTR + cd]     = *(const uint4*)(qg + g);
        *(uint4*)&Qb[cq * QSTR + cd + 8] = *(const uint4*)(qg + g + 8);
    }
    __syncthreads();

    // P2: local scores -> S[q][268+l]
    {
        int q = tid >> 2, l = tid & 3;
        if (l < 3) {
            int i = 4 * (q0 + q) + r, j = i - 1 - l;
            float s = -1e30f;
            if (j >= 0) {
                size_t kgo = (((size_t)bh * 4 + (j & 3)) * 256 + (j >> 2)) * 64;
                float acc = 0.f;
#pragma unroll
                for (int d = 0; d < 64; d += 2) {
                    __half2 qv = *(const __half2*)&Qb[q * QSTR + d];
                    __half2 kv = *(const __half2*)(kg + kgo + d);
                    acc += __half2float(qv.x) * __half2float(kv.x)
                         + __half2float(qv.y) * __half2float(kv.y);
                }
                s = acc * 0.125f;
            }
            S[q * SROW + 268 + l] = s;
        }
    }

    // MMA maps
    const int wm = (w & 3) * 16, wn = (w >> 2) * 32;
    const int lrow = lane & 15, lcol = (lane >> 4) << 3;
    const int bnrow = ((lane >> 4) << 3) + (lane & 7);   // B non-trans row
    const int bkoff = ((lane >> 3) & 1) << 3;            // B non-trans k-off
    const int g8 = lane >> 2, t4 = lane & 3;

    // P3: score MMA over k-tiles
    for (int ut = 0; ut < ntiles; ut++) {
        __syncthreads();
        {
            size_t g = (((size_t)bh * 4 + r) * 256 + ut * 64 + cq) * 64 + cd;
            *(uint4*)&Kb[cq * QSTR + cd]     = *(const uint4*)(kg + g);
            *(uint4*)&Kb[cq * QSTR + cd + 8] = *(const uint4*)(kg + g + 8);
        }
        __syncthreads();

        float acc[4][4];
#pragma unroll
        for (int a = 0; a < 4; a++)
#pragma unroll
            for (int b = 0; b < 4; b++) acc[a][b] = 0.f;

#pragma unroll
        for (int ks = 0; ks < 4; ks++) {
            uint32_t ah[4];
            ldm_x4(ah, &Qb[(wm + lrow) * QSTR + ks * 16 + lcol]);
#pragma unroll
            for (int half = 0; half < 2; half++) {
                uint32_t bh4[4];
                ldm_x4(bh4, &Kb[(wn + half * 16 + bnrow) * QSTR + ks * 16 + bkoff]);
#pragma unroll
                for (int sub = 0; sub < 2; sub++)
                    mma16816(acc[half * 2 + sub], ah, &bh4[sub * 2]);
            }
        }
        // epilogue: mask + scale -> S fp32
#pragma unroll
        for (int nt = 0; nt < 4; nt++) {
            int ug = ut * 64 + wn + nt * 8 + t4 * 2;
#pragma unroll
            for (int rr = 0; rr < 2; rr++) {
                int qloc = wm + g8 + rr * 8;
                int qg2 = q0 + qloc;
                S[qloc * SROW + ug]     = (ug     <= qg2) ? acc[nt][rr * 2]     * 0.125f : -1e30f;
                S[qloc * SROW + ug + 1] = (ug + 1 <= qg2) ? acc[nt][rr * 2 + 1] * 0.125f : -1e30f;
            }
        }
    }
    __syncthreads();

    // P4: softmax; rewrite rows in place as packed fp16 P (bytes [0,512))
    {
        const int klim = ntiles * 64;
        for (int q = w * 8; q < w * 8 + 8; q++) {
            float vals[8];
            int nv = 0;
            float mx = -1e30f;
            for (int t = lane; t < klim; t += 32) {
                float s = S[q * SROW + t];
                vals[nv++] = s;
                mx = fmaxf(mx, s);
            }
            float lv = (lane < 3) ? S[q * SROW + 268 + lane] : -1e30f;
            mx = fmaxf(mx, lv);
#pragma unroll
            for (int o = 16; o; o >>= 1) mx = fmaxf(mx, __shfl_xor_sync(0xffffffffu, mx, o));
            __syncwarp();
            __half* Ph = (__half*)((char*)S + (size_t)q * SROW * 4);
            float sum = 0.f;
            nv = 0;
            for (int t = lane; t < klim; t += 32) {
                float e = __expf(vals[nv++] - mx);
                sum += e;
                Ph[t] = __float2half(e);
            }
            if (lane < 3) {
                float e = __expf(lv - mx);
                sum += e;
                S[q * SROW + 268 + lane] = e;
            }
#pragma unroll
            for (int o = 16; o; o >>= 1) sum += __shfl_xor_sync(0xffffffffu, sum, o);
            if (lane == 0) Ssum[q] = sum;
        }
    }

    // P5: PV MMA (V reuses Kb)
    float oacc[4][4];
#pragma unroll
    for (int a = 0; a < 4; a++)
#pragma unroll
        for (int b = 0; b < 4; b++) oacc[a][b] = 0.f;

    for (int ut = 0; ut < ntiles; ut++) {
        __syncthreads();
        {
            size_t g = (((size_t)bh * 4 + r) * 256 + ut * 64 + cq) * 64 + cd;
            *(uint4*)&Kb[cq * QSTR + cd]     = *(const uint4*)(vg + g);
            *(uint4*)&Kb[cq * QSTR + cd + 8] = *(const uint4*)(vg + g + 8);
        }
        __syncthreads();

#pragma unroll
        for (int ks = 0; ks < 4; ks++) {
            uint32_t ph4[4];
            char* prow = (char*)S + (size_t)(wm + lrow) * SROW * 4;
            int kc = ut * 64 + ks * 16 + lcol;
            ldm_x4(ph4, prow + 2 * kc);
#pragma unroll
            for (int half = 0; half < 2; half++) {
                uint32_t vh4[4];
                ldm_x4_t(vh4, &Kb[(ks * 16 + lrow) * QSTR + wn + half * 16 + lcol]);
#pragma unroll
                for (int sub = 0; sub < 2; sub++)
                    mma16816(oacc[half * 2 + sub], ph4, &vh4[sub * 2]);
            }
        }
    }
    __syncthreads();   // all Qb/Kb uses done; safe to overwrite as Osm
#pragma unroll
    for (int nt = 0; nt < 4; nt++) {
        int dcol = wn + nt * 8 + t4 * 2;
        Osm[(wm + g8) * 68 + dcol]         = oacc[nt][0];
        Osm[(wm + g8) * 68 + dcol + 1]     = oacc[nt][1];
        Osm[(wm + g8 + 8) * 68 + dcol]     = oacc[nt][2];
        Osm[(wm + g8 + 8) * 68 + dcol + 1] = oacc[nt][3];
    }
    __syncthreads();

    // P6: locals PV + normalize + write
    {
        int q = cq, dseg = cd;
        int i = 4 * (q0 + q) + r;
        float inv = 1.0f / Ssum[q];
        float o[16];
#pragma unroll
        for (int d = 0; d < 16; d++) o[d] = Osm[q * 68 + dseg + d];
#pragma unroll
        for (int l = 0; l < 3; l++) {
            int j = i - 1 - l;
            if (j >= 0) {
                float p = S[q * SROW + 268 + l];
                size_t vgo = (((size_t)bh * 4 + (j & 3)) * 256 + (j >> 2)) * 64 + dseg;
#pragma unroll
                for (int d = 0; d < 16; d += 2) {
                    __half2 a = *(const __half2*)(vg + vgo + d);
                    o[d]     += p * __half2float(a.x);
                    o[d + 1] += p * __half2float(a.y);
                }
            }
        }
        int bb = bh >> 4, h = bh & 15;
        float* op = out + ((size_t)(bb * 1024 + i)) * 1024 + h * 64 + dseg;
#pragma unroll
        for (int d = 0; d < 16; d += 4)
            *(float4*)(op + d) = make_float4(o[d] * inv, o[d + 1] * inv, o[d + 2] * inv, o[d + 3] * inv);
    }
}

// ---------------------------------------------------------------------------
extern "C" void kernel_launch(void* const* d_in, const int* in_sizes, int n_in,
                              void* d_out, int out_size)
{
    const float* Q  = (const float*)d_in[0];
    const float* K  = (const float*)d_in[1];
    const float* V  = (const float*)d_in[2];
    const float* Wq = (const float*)d_in[3];
    const float* bq = (const float*)d_in[4];
    const float* Wk = (const float*)d_in[5];
    const float* bk = (const float*)d_in[6];
    const float* Wv = (const float*)d_in[7];
    const float* bv = (const float*)d_in[8];
    const float* Wo = (const float*)d_in[9];
    const float* bo = (const float*)d_in[10];
    float* out = (float*)d_out;

    __half *pq, *pk, *pv;
    float* pa;
    cudaGetSymbolAddress((void**)&pq, g_q);
    cudaGetSymbolAddress((void**)&pk, g_k);
    cudaGetSymbolAddress((void**)&pv, g_v);
    cudaGetSymbolAddress((void**)&pa, g_attn);

    cudaFuncSetAttribute(gemm_half_kernel,
                         cudaFuncAttributeMaxDynamicSharedMemorySize, GEMM_SMEM);
    cudaFuncSetAttribute(attn_mma_kernel,
                         cudaFuncAttributeMaxDynamicSharedMemorySize, ATTN_SMEM);

    dim3 gg(8, 32);
    dim3 tb(256);

    gemm_half_kernel<<<gg, tb, GEMM_SMEM>>>(Q, Wq, bq, nullptr, pq, 1);
    gemm_half_kernel<<<gg, tb, GEMM_SMEM>>>(K, Wk, bk, nullptr, pk, 2);
    gemm_half_kernel<<<gg, tb, GEMM_SMEM>>>(V, Wv, bv, nullptr, pv, 2);

    attn_mma_kernel<<<1024, 256, ATTN_SMEM>>>(pq, pk, pv, pa);

    gemm_half_kernel<<<gg, tb, GEMM_SMEM>>>(pa, Wo, bo, out, nullptr, 0);
}

// round 7
// speedup vs baseline: 4.5872x; 1.1605x over previous
#include <cuda_runtime.h>
#include <cuda_fp16.h>
#include <cstdint>

#define BB 4
#define SS 1024
#define DD 1024
#define HH 16
#define DK 64
#define NEL (BB * HH * SS * DK)   // 4M

// Scratch (__device__ globals)
__device__ __half g_qin[NEL], g_kin[NEL], g_vin[NEL];   // fp16 input copies [B,S,D]
__device__ __half g_w[4 * DD * DD];                     // fp16 weights [k][n] (4 mats)
__device__ __half g_q[NEL];          // [bh][s][d]
__device__ __half g_k[NEL];          // [bh][r][u][d]
__device__ __half g_v[NEL];          // [bh][r][u][d]
__device__ __half g_attn[BB * SS * DD];                 // fp16 attention out [B,S,D]

// ---------------------------------------------------------------------------
__device__ __forceinline__ unsigned saddr(const void* p) {
    return (unsigned)__cvta_generic_to_shared(p);
}
__device__ __forceinline__ void ldm_x4(uint32_t* r, const void* p) {
    asm volatile("ldmatrix.sync.aligned.m8n8.x4.shared.b16 {%0,%1,%2,%3}, [%4];"
        : "=r"(r[0]), "=r"(r[1]), "=r"(r[2]), "=r"(r[3]) : "r"(saddr(p)));
}
__device__ __forceinline__ void ldm_x4_t(uint32_t* r, const void* p) {
    asm volatile("ldmatrix.sync.aligned.m8n8.x4.trans.shared.b16 {%0,%1,%2,%3}, [%4];"
        : "=r"(r[0]), "=r"(r[1]), "=r"(r[2]), "=r"(r[3]) : "r"(saddr(p)));
}
__device__ __forceinline__ void mma16816(float* c, const uint32_t* a, const uint32_t* b) {
    asm volatile("mma.sync.aligned.m16n8k16.row.col.f32.f16.f16.f32 "
        "{%0,%1,%2,%3},{%4,%5,%6,%7},{%8,%9},{%0,%1,%2,%3};"
        : "+f"(c[0]), "+f"(c[1]), "+f"(c[2]), "+f"(c[3])
        : "r"(a[0]), "r"(a[1]), "r"(a[2]), "r"(a[3]), "r"(b[0]), "r"(b[1]));
}
__device__ __forceinline__ void cp_async16(void* s, const void* g) {
    asm volatile("cp.async.cg.shared.global [%0], [%1], 16;"
        :: "r"(saddr(s)), "l"(g));
}
#define CP_COMMIT() asm volatile("cp.async.commit_group;" ::: "memory")
#define CP_WAIT0()  asm volatile("cp.async.wait_group 0;" ::: "memory")

// ---------------------------------------------------------------------------
// Prep: fp32 -> fp16 elementwise (4 elems/thread)
// ---------------------------------------------------------------------------
__global__ void __launch_bounds__(256) conv_kernel(
    const float* __restrict__ src, __half* __restrict__ dst)
{
    int i = blockIdx.x * 256 + threadIdx.x;
    float4 v = *(const float4*)(src + (size_t)i * 4);
    __half2 a = __floats2half2_rn(v.x, v.y);
    __half2 b = __floats2half2_rn(v.z, v.w);
    uint2 u; u.x = *(uint32_t*)&a; u.y = *(uint32_t*)&b;
    *(uint2*)(dst + (size_t)i * 4) = u;
}

// ---------------------------------------------------------------------------
// fp16 GEMM with cp.async double-buffered staging.
// C = A[4096,1024](fp16,[m][k]) @ W[1024,1024](fp16,[k][n]) + bias
// mode 0: fp32 C[m*1024+n]
// mode 1: fp16 O, idx = ((b*16+h)*1024+s)*64+d
// mode 2: fp16 O, idx = (((b*16+h)*4+(s&3))*256+(s>>2))*64+d
// ---------------------------------------------------------------------------
#define APAD 48
#define WPAD 144
#define A_SZ (128 * APAD)    // halfs per buffer
#define W_SZ (32 * WPAD)
#define GEMM_SMEM ((2 * A_SZ + 2 * W_SZ) * 2)   // bytes

__device__ __forceinline__ void store2(
    float* __restrict__ C, __half* __restrict__ O, int mode,
    int m, int n, float v0, float v1)
{
    if (mode == 0) {
        *(float2*)(C + (size_t)m * 1024 + n) = make_float2(v0, v1);
        return;
    }
    int b = m >> 10, s = m & 1023, h = n >> 6, d = n & 63;
    size_t idx;
    if (mode == 1) idx = (((size_t)(b * 16 + h)) * 1024 + s) * 64 + d;
    else           idx = ((((size_t)(b * 16 + h)) * 4 + (s & 3)) * 256 + (s >> 2)) * 64 + d;
    __half2 p = __floats2half2_rn(v0, v1);
    *(__half2*)(O + idx) = p;
}

__global__ void __launch_bounds__(256) gemm_cp_kernel(
    const __half* __restrict__ A, const __half* __restrict__ Wm,
    const float* __restrict__ bias, float* __restrict__ C,
    __half* __restrict__ O, int mode)
{
    extern __shared__ __half smem[];
    __half* sA = smem;                 // [2][128][APAD]
    __half* sW = smem + 2 * A_SZ;      // [2][32][WPAD]

    const int tid = threadIdx.x;
    const int bm = blockIdx.y * 128, bn = blockIdx.x * 128;
    const int w = tid >> 5, lane = tid & 31;
    const int wm = (w & 1) * 64, wn = (w >> 1) * 32;
    const int lrow = lane & 15, lcol = (lane >> 4) << 3;

    // copy maps: A = 512 chunks of 16B (128 rows x 4), W = 512 chunks (32 rows x 16)
    const int ac0 = tid * 2;
    const int ar0 = ac0 >> 2,  aco0 = (ac0 & 3) * 8;
    const int ar1 = (ac0 + 1) >> 2, aco1 = ((ac0 + 1) & 3) * 8;
    const int wr0 = ac0 >> 4,  wco0 = (ac0 & 15) * 8;
    const int wr1 = (ac0 + 1) >> 4, wco1 = ((ac0 + 1) & 15) * 8;

    float acc[4][4][4];
#pragma unroll
    for (int i = 0; i < 4; i++)
#pragma unroll
        for (int j = 0; j < 4; j++)
#pragma unroll
            for (int t = 0; t < 4; t++) acc[i][j][t] = 0.f;

    // stage tile k0 into buffer buf
    auto stage = [&](int buf, int k0) {
        cp_async16(&sA[buf * A_SZ + ar0 * APAD + aco0],
                   A + (size_t)(bm + ar0) * 1024 + k0 + aco0);
        cp_async16(&sA[buf * A_SZ + ar1 * APAD + aco1],
                   A + (size_t)(bm + ar1) * 1024 + k0 + aco1);
        cp_async16(&sW[buf * W_SZ + wr0 * WPAD + wco0],
                   Wm + (size_t)(k0 + wr0) * 1024 + bn + wco0);
        cp_async16(&sW[buf * W_SZ + wr1 * WPAD + wco1],
                   Wm + (size_t)(k0 + wr1) * 1024 + bn + wco1);
    };

    stage(0, 0);
    CP_COMMIT();
    CP_WAIT0();
    __syncthreads();

    int buf = 0;
    for (int k0 = 0; k0 < 1024; k0 += 32) {
        const bool next = (k0 + 32 < 1024);
        if (next) {
            stage(buf ^ 1, k0 + 32);
            CP_COMMIT();
        }

        const __half* cA = sA + buf * A_SZ;
        const __half* cW = sW + buf * W_SZ;

#pragma unroll
        for (int kk = 0; kk < 32; kk += 16) {
            uint32_t a[4][4], b_[2][4];
#pragma unroll
            for (int mt = 0; mt < 4; mt++)
                ldm_x4(a[mt], &cA[(wm + mt * 16 + lrow) * APAD + kk + lcol]);
#pragma unroll
            for (int np = 0; np < 2; np++)
                ldm_x4_t(b_[np], &cW[(kk + lrow) * WPAD + wn + np * 16 + lcol]);
#pragma unroll
            for (int mt = 0; mt < 4; mt++)
#pragma unroll
                for (int nt = 0; nt < 4; nt++)
                    mma16816(acc[mt][nt], a[mt], &b_[nt >> 1][(nt & 1) * 2]);
        }

        if (next) CP_WAIT0();
        __syncthreads();
        buf ^= 1;
    }

    const int g = lane >> 2, t4 = lane & 3;
#pragma unroll
    for (int mt = 0; mt < 4; mt++)
#pragma unroll
        for (int nt = 0; nt < 4; nt++) {
            int m0 = bm + wm + mt * 16 + g;
            int n0 = bn + wn + nt * 8 + t4 * 2;
            float b0 = __ldg(bias + n0), b1 = __ldg(bias + n0 + 1);
            store2(C, O, mode, m0,     n0, acc[mt][nt][0] + b0, acc[mt][nt][1] + b1);
            store2(C, O, mode, m0 + 8, n0, acc[mt][nt][2] + b0, acc[mt][nt][3] + b1);
        }
}

// ---------------------------------------------------------------------------
// Tensor-core sparse attention, fp16 single-pass (R5 design, fp16 output).
// Block = (bh, r, qt): 64 queries i = 4*(q0+q)+r.
// smem (floats): S [64][276]=17664 | Qb (2304) | Kb (2304) | Ssum (64)
// ---------------------------------------------------------------------------
#define SROW 276
#define QSTR 72
#define ATTN_SMEM ((64 * SROW + 2304 + 2304 + 64) * 4)

__global__ void __launch_bounds__(256) attn_mma_kernel(
    const __half* __restrict__ qg, const __half* __restrict__ kg,
    const __half* __restrict__ vg, __half* __restrict__ out)
{
    extern __shared__ float sm[];
    float* S = sm;
    __half* Qb = (__half*)(sm + 64 * SROW);
    __half* Kb = (__half*)(sm + 64 * SROW + 2304);
    float* Ssum = sm + 64 * SROW + 4608;
    float* Osm  = (float*)Qb;

    const int tid = threadIdx.x, lane = tid & 31, w = tid >> 5;
    const int qt = 3 - (blockIdx.x >> 8);
    const int bh = (blockIdx.x & 255) >> 2;
    const int r  = blockIdx.x & 3;
    const int q0 = qt * 64;
    const int ntiles = qt + 1;

    const int cq = tid >> 2, cd = (tid & 3) * 16;

    {
        int i = 4 * (q0 + cq) + r;
        size_t g = ((size_t)bh * 1024 + i) * 64 + cd;
        *(uint4*)&Qb[cq * QSTR + cd]     = *(const uint4*)(qg + g);
        *(uint4*)&Qb[cq * QSTR + cd + 8] = *(const uint4*)(qg + g + 8);
    }
    __syncthreads();

    {
        int q = tid >> 2, l = tid & 3;
        if (l < 3) {
            int i = 4 * (q0 + q) + r, j = i - 1 - l;
            float s = -1e30f;
            if (j >= 0) {
                size_t kgo = (((size_t)bh * 4 + (j & 3)) * 256 + (j >> 2)) * 64;
                float acc = 0.f;
#pragma unroll
                for (int d = 0; d < 64; d += 2) {
                    __half2 qv = *(const __half2*)&Qb[q * QSTR + d];
                    __half2 kv = *(const __half2*)(kg + kgo + d);
                    acc += __half2float(qv.x) * __half2float(kv.x)
                         + __half2float(qv.y) * __half2float(kv.y);
                }
                s = acc * 0.125f;
            }
            S[q * SROW + 268 + l] = s;
        }
    }

    const int wm = (w & 3) * 16, wn = (w >> 2) * 32;
    const int lrow = lane & 15, lcol = (lane >> 4) << 3;
    const int bnrow = ((lane >> 4) << 3) + (lane & 7);
    const int bkoff = ((lane >> 3) & 1) << 3;
    const int g8 = lane >> 2, t4 = lane & 3;

    for (int ut = 0; ut < ntiles; ut++) {
        __syncthreads();
        {
            size_t g = (((size_t)bh * 4 + r) * 256 + ut * 64 + cq) * 64 + cd;
            *(uint4*)&Kb[cq * QSTR + cd]     = *(const uint4*)(kg + g);
            *(uint4*)&Kb[cq * QSTR + cd + 8] = *(const uint4*)(kg + g + 8);
        }
        __syncthreads();

        float acc[4][4];
#pragma unroll
        for (int a = 0; a < 4; a++)
#pragma unroll
            for (int b = 0; b < 4; b++) acc[a][b] = 0.f;

#pragma unroll
        for (int ks = 0; ks < 4; ks++) {
            uint32_t ah[4];
            ldm_x4(ah, &Qb[(wm + lrow) * QSTR + ks * 16 + lcol]);
#pragma unroll
            for (int half = 0; half < 2; half++) {
                uint32_t bh4[4];
                ldm_x4(bh4, &Kb[(wn + half * 16 + bnrow) * QSTR + ks * 16 + bkoff]);
#pragma unroll
                for (int sub = 0; sub < 2; sub++)
                    mma16816(acc[half * 2 + sub], ah, &bh4[sub * 2]);
            }
        }
#pragma unroll
        for (int nt = 0; nt < 4; nt++) {
            int ug = ut * 64 + wn + nt * 8 + t4 * 2;
#pragma unroll
            for (int rr = 0; rr < 2; rr++) {
                int qloc = wm + g8 + rr * 8;
                int qg2 = q0 + qloc;
                S[qloc * SROW + ug]     = (ug     <= qg2) ? acc[nt][rr * 2]     * 0.125f : -1e30f;
                S[qloc * SROW + ug + 1] = (ug + 1 <= qg2) ? acc[nt][rr * 2 + 1] * 0.125f : -1e30f;
            }
        }
    }
    __syncthreads();

    {
        const int klim = ntiles * 64;
        for (int q = w * 8; q < w * 8 + 8; q++) {
            float vals[8];
            int nv = 0;
            float mx = -1e30f;
            for (int t = lane; t < klim; t += 32) {
                float s = S[q * SROW + t];
                vals[nv++] = s;
                mx = fmaxf(mx, s);
            }
            float lv = (lane < 3) ? S[q * SROW + 268 + lane] : -1e30f;
            mx = fmaxf(mx, lv);
#pragma unroll
            for (int o = 16; o; o >>= 1) mx = fmaxf(mx, __shfl_xor_sync(0xffffffffu, mx, o));
            __syncwarp();
            __half* Ph = (__half*)((char*)S + (size_t)q * SROW * 4);
            float sum = 0.f;
            nv = 0;
            for (int t = lane; t < klim; t += 32) {
                float e = __expf(vals[nv++] - mx);
                sum += e;
                Ph[t] = __float2half(e);
            }
            if (lane < 3) {
                float e = __expf(lv - mx);
                sum += e;
                S[q * SROW + 268 + lane] = e;
            }
#pragma unroll
            for (int o = 16; o; o >>= 1) sum += __shfl_xor_sync(0xffffffffu, sum, o);
            if (lane == 0) Ssum[q] = sum;
        }
    }

    float oacc[4][4];
#pragma unroll
    for (int a = 0; a < 4; a++)
#pragma unroll
        for (int b = 0; b < 4; b++) oacc[a][b] = 0.f;

    for (int ut = 0; ut < ntiles; ut++) {
        __syncthreads();
        {
            size_t g = (((size_t)bh * 4 + r) * 256 + ut * 64 + cq) * 64 + cd;
            *(uint4*)&Kb[cq * QSTR + cd]     = *(const uint4*)(vg + g);
            *(uint4*)&Kb[cq * QSTR + cd + 8] = *(const uint4*)(vg + g + 8);
        }
        __syncthreads();

#pragma unroll
        for (int ks = 0; ks < 4; ks++) {
            uint32_t ph4[4];
            char* prow = (char*)S + (size_t)(wm + lrow) * SROW * 4;
            int kc = ut * 64 + ks * 16 + lcol;
            ldm_x4(ph4, prow + 2 * kc);
#pragma unroll
            for (int half = 0; half < 2; half++) {
                uint32_t vh4[4];
                ldm_x4_t(vh4, &Kb[(ks * 16 + lrow) * QSTR + wn + half * 16 + lcol]);
#pragma unroll
                for (int sub = 0; sub < 2; sub++)
                    mma16816(oacc[half * 2 + sub], ph4, &vh4[sub * 2]);
            }
        }
    }
    __syncthreads();
#pragma unroll
    for (int nt = 0; nt < 4; nt++) {
        int dcol = wn + nt * 8 + t4 * 2;
        Osm[(wm + g8) * 68 + dcol]         = oacc[nt][0];
        Osm[(wm + g8) * 68 + dcol + 1]     = oacc[nt][1];
        Osm[(wm + g8 + 8) * 68 + dcol]     = oacc[nt][2];
        Osm[(wm + g8 + 8) * 68 + dcol + 1] = oacc[nt][3];
    }
    __syncthreads();

    {
        int q = cq, dseg = cd;
        int i = 4 * (q0 + q) + r;
        float inv = 1.0f / Ssum[q];
        float o[16];
#pragma unroll
        for (int d = 0; d < 16; d++) o[d] = Osm[q * 68 + dseg + d];
#pragma unroll
        for (int l = 0; l < 3; l++) {
            int j = i - 1 - l;
            if (j >= 0) {
                float p = S[q * SROW + 268 + l];
                size_t vgo = (((size_t)bh * 4 + (j & 3)) * 256 + (j >> 2)) * 64 + dseg;
#pragma unroll
                for (int d = 0; d < 16; d += 2) {
                    __half2 a = *(const __half2*)(vg + vgo + d);
                    o[d]     += p * __half2float(a.x);
                    o[d + 1] += p * __half2float(a.y);
                }
            }
        }
        int bb = bh >> 4, h = bh & 15;
        __half* op = out + ((size_t)(bb * 1024 + i)) * 1024 + h * 64 + dseg;
#pragma unroll
        for (int d = 0; d < 16; d += 2) {
            __half2 p = __floats2half2_rn(o[d] * inv, o[d + 1] * inv);
            *(__half2*)(op + d) = p;
        }
    }
}

// ---------------------------------------------------------------------------
extern "C" void kernel_launch(void* const* d_in, const int* in_sizes, int n_in,
                              void* d_out, int out_size)
{
    const float* Q  = (const float*)d_in[0];
    const float* K  = (const float*)d_in[1];
    const float* V  = (const float*)d_in[2];
    const float* Wq = (const float*)d_in[3];
    const float* bq = (const float*)d_in[4];
    const float* Wk = (const float*)d_in[5];
    const float* bk = (const float*)d_in[6];
    const float* Wv = (const float*)d_in[7];
    const float* bv = (const float*)d_in[8];
    const float* Wo = (const float*)d_in[9];
    const float* bo = (const float*)d_in[10];
    float* out = (float*)d_out;

    __half *pqin, *pkin, *pvin, *pw, *pq, *pk, *pv, *pah;
    cudaGetSymbolAddress((void**)&pqin, g_qin);
    cudaGetSymbolAddress((void**)&pkin, g_kin);
    cudaGetSymbolAddress((void**)&pvin, g_vin);
    cudaGetSymbolAddress((void**)&pw, g_w);
    cudaGetSymbolAddress((void**)&pq, g_q);
    cudaGetSymbolAddress((void**)&pk, g_k);
    cudaGetSymbolAddress((void**)&pv, g_v);
    cudaGetSymbolAddress((void**)&pah, g_attn);

    cudaFuncSetAttribute(gemm_cp_kernel,
                         cudaFuncAttributeMaxDynamicSharedMemorySize, GEMM_SMEM);
    cudaFuncSetAttribute(attn_mma_kernel,
                         cudaFuncAttributeMaxDynamicSharedMemorySize, ATTN_SMEM);

    // prep: fp16 conversions (inputs 4M elems -> 4096 blocks; weights 1M -> 1024)
    conv_kernel<<<4096, 256>>>(Q, pqin);
    conv_kernel<<<4096, 256>>>(K, pkin);
    conv_kernel<<<4096, 256>>>(V, pvin);
    conv_kernel<<<1024, 256>>>(Wq, pw);
    conv_kernel<<<1024, 256>>>(Wk, pw + 1 * DD * DD);
    conv_kernel<<<1024, 256>>>(Wv, pw + 2 * DD * DD);
    conv_kernel<<<1024, 256>>>(Wo, pw + 3 * DD * DD);

    dim3 gg(8, 32);
    dim3 tb(256);

    gemm_cp_kernel<<<gg, tb, GEMM_SMEM>>>(pqin, pw,               bq, nullptr, pq, 1);
    gemm_cp_kernel<<<gg, tb, GEMM_SMEM>>>(pkin, pw + 1 * DD * DD, bk, nullptr, pk, 2);
    gemm_cp_kernel<<<gg, tb, GEMM_SMEM>>>(pvin, pw + 2 * DD * DD, bv, nullptr, pv, 2);

    attn_mma_kernel<<<1024, 256, ATTN_SMEM>>>(pq, pk, pv, pah);

    gemm_cp_kernel<<<gg, tb, GEMM_SMEM>>>(pah, pw + 3 * DD * DD, bo, out, nullptr, 0);
}

// round 8
// speedup vs baseline: 5.6789x; 1.2380x over previous
#include <cuda_runtime.h>
#include <cuda_fp16.h>
#include <cstdint>

#define BB 4
#define SS 1024
#define DD 1024
#define HH 16
#define DK 64
#define NEL (BB * HH * SS * DK)   // 4M

// Scratch (__device__ globals)
__device__ __half g_qin[NEL], g_kin[NEL], g_vin[NEL];   // fp16 input copies [B,S,D]
__device__ __half g_w[4 * DD * DD];                     // fp16 weights [k][n] (4 mats)
__device__ __half g_q[NEL];          // [bh][s][d]
__device__ __half g_k[NEL];          // [bh][r][u][d]
__device__ __half g_v[NEL];          // [bh][r][u][d]
__device__ __half g_attn[BB * SS * DD];                 // fp16 attention out [B,S,D]

// ---------------------------------------------------------------------------
__device__ __forceinline__ unsigned saddr(const void* p) {
    return (unsigned)__cvta_generic_to_shared(p);
}
__device__ __forceinline__ void ldm_x4(uint32_t* r, const void* p) {
    asm volatile("ldmatrix.sync.aligned.m8n8.x4.shared.b16 {%0,%1,%2,%3}, [%4];"
        : "=r"(r[0]), "=r"(r[1]), "=r"(r[2]), "=r"(r[3]) : "r"(saddr(p)));
}
__device__ __forceinline__ void ldm_x4_t(uint32_t* r, const void* p) {
    asm volatile("ldmatrix.sync.aligned.m8n8.x4.trans.shared.b16 {%0,%1,%2,%3}, [%4];"
        : "=r"(r[0]), "=r"(r[1]), "=r"(r[2]), "=r"(r[3]) : "r"(saddr(p)));
}
__device__ __forceinline__ void mma16816(float* c, const uint32_t* a, const uint32_t* b) {
    asm volatile("mma.sync.aligned.m16n8k16.row.col.f32.f16.f16.f32 "
        "{%0,%1,%2,%3},{%4,%5,%6,%7},{%8,%9},{%0,%1,%2,%3};"
        : "+f"(c[0]), "+f"(c[1]), "+f"(c[2]), "+f"(c[3])
        : "r"(a[0]), "r"(a[1]), "r"(a[2]), "r"(a[3]), "r"(b[0]), "r"(b[1]));
}
__device__ __forceinline__ void cp_async16(void* s, const void* g) {
    asm volatile("cp.async.cg.shared.global [%0], [%1], 16;"
        :: "r"(saddr(s)), "l"(g));
}
#define CP_COMMIT() asm volatile("cp.async.commit_group;" ::: "memory")
#define CP_WAIT0()  asm volatile("cp.async.wait_group 0;" ::: "memory")

__device__ __forceinline__ uint32_t packh2(float a, float b) {
    __half2 p = __floats2half2_rn(a, b);
    return *(uint32_t*)&p;
}

// ---------------------------------------------------------------------------
// Prep: fp32 -> fp16, batched by blockIdx.y
// ---------------------------------------------------------------------------
__global__ void __launch_bounds__(256) conv3_kernel(
    const float* __restrict__ s0, const float* __restrict__ s1,
    const float* __restrict__ s2, __half* __restrict__ d0,
    __half* __restrict__ d1, __half* __restrict__ d2)
{
    const float* src = (blockIdx.y == 0) ? s0 : (blockIdx.y == 1) ? s1 : s2;
    __half* dst = (blockIdx.y == 0) ? d0 : (blockIdx.y == 1) ? d1 : d2;
    int i = blockIdx.x * 256 + threadIdx.x;
    float4 v = *(const float4*)(src + (size_t)i * 4);
    uint2 u; u.x = packh2(v.x, v.y); u.y = packh2(v.z, v.w);
    *(uint2*)(dst + (size_t)i * 4) = u;
}

__global__ void __launch_bounds__(256) conv4_kernel(
    const float* __restrict__ s0, const float* __restrict__ s1,
    const float* __restrict__ s2, const float* __restrict__ s3,
    __half* __restrict__ dst)
{
    const float* src = (blockIdx.y == 0) ? s0 : (blockIdx.y == 1) ? s1
                     : (blockIdx.y == 2) ? s2 : s3;
    __half* d = dst + (size_t)blockIdx.y * DD * DD;
    int i = blockIdx.x * 256 + threadIdx.x;
    float4 v = *(const float4*)(src + (size_t)i * 4);
    uint2 u; u.x = packh2(v.x, v.y); u.y = packh2(v.z, v.w);
    *(uint2*)(d + (size_t)i * 4) = u;
}

// ---------------------------------------------------------------------------
// fp16 GEMM with cp.async double-buffered staging (unchanged from R7).
// ---------------------------------------------------------------------------
#define APAD 48
#define WPAD 144
#define A_SZ (128 * APAD)
#define W_SZ (32 * WPAD)
#define GEMM_SMEM ((2 * A_SZ + 2 * W_SZ) * 2)

__device__ __forceinline__ void store2(
    float* __restrict__ C, __half* __restrict__ O, int mode,
    int m, int n, float v0, float v1)
{
    if (mode == 0) {
        *(float2*)(C + (size_t)m * 1024 + n) = make_float2(v0, v1);
        return;
    }
    int b = m >> 10, s = m & 1023, h = n >> 6, d = n & 63;
    size_t idx;
    if (mode == 1) idx = (((size_t)(b * 16 + h)) * 1024 + s) * 64 + d;
    else           idx = ((((size_t)(b * 16 + h)) * 4 + (s & 3)) * 256 + (s >> 2)) * 64 + d;
    __half2 p = __floats2half2_rn(v0, v1);
    *(__half2*)(O + idx) = p;
}

__global__ void __launch_bounds__(256) gemm_cp_kernel(
    const __half* __restrict__ A, const __half* __restrict__ Wm,
    const float* __restrict__ bias, float* __restrict__ C,
    __half* __restrict__ O, int mode)
{
    extern __shared__ __half smem[];
    __half* sA = smem;
    __half* sW = smem + 2 * A_SZ;

    const int tid = threadIdx.x;
    const int bm = blockIdx.y * 128, bn = blockIdx.x * 128;
    const int w = tid >> 5, lane = tid & 31;
    const int wm = (w & 1) * 64, wn = (w >> 1) * 32;
    const int lrow = lane & 15, lcol = (lane >> 4) << 3;

    const int ac0 = tid * 2;
    const int ar0 = ac0 >> 2,  aco0 = (ac0 & 3) * 8;
    const int ar1 = (ac0 + 1) >> 2, aco1 = ((ac0 + 1) & 3) * 8;
    const int wr0 = ac0 >> 4,  wco0 = (ac0 & 15) * 8;
    const int wr1 = (ac0 + 1) >> 4, wco1 = ((ac0 + 1) & 15) * 8;

    float acc[4][4][4];
#pragma unroll
    for (int i = 0; i < 4; i++)
#pragma unroll
        for (int j = 0; j < 4; j++)
#pragma unroll
            for (int t = 0; t < 4; t++) acc[i][j][t] = 0.f;

    auto stage = [&](int buf, int k0) {
        cp_async16(&sA[buf * A_SZ + ar0 * APAD + aco0],
                   A + (size_t)(bm + ar0) * 1024 + k0 + aco0);
        cp_async16(&sA[buf * A_SZ + ar1 * APAD + aco1],
                   A + (size_t)(bm + ar1) * 1024 + k0 + aco1);
        cp_async16(&sW[buf * W_SZ + wr0 * WPAD + wco0],
                   Wm + (size_t)(k0 + wr0) * 1024 + bn + wco0);
        cp_async16(&sW[buf * W_SZ + wr1 * WPAD + wco1],
                   Wm + (size_t)(k0 + wr1) * 1024 + bn + wco1);
    };

    stage(0, 0);
    CP_COMMIT();
    CP_WAIT0();
    __syncthreads();

    int buf = 0;
    for (int k0 = 0; k0 < 1024; k0 += 32) {
        const bool next = (k0 + 32 < 1024);
        if (next) {
            stage(buf ^ 1, k0 + 32);
            CP_COMMIT();
        }

        const __half* cA = sA + buf * A_SZ;
        const __half* cW = sW + buf * W_SZ;

#pragma unroll
        for (int kk = 0; kk < 32; kk += 16) {
            uint32_t a[4][4], b_[2][4];
#pragma unroll
            for (int mt = 0; mt < 4; mt++)
                ldm_x4(a[mt], &cA[(wm + mt * 16 + lrow) * APAD + kk + lcol]);
#pragma unroll
            for (int np = 0; np < 2; np++)
                ldm_x4_t(b_[np], &cW[(kk + lrow) * WPAD + wn + np * 16 + lcol]);
#pragma unroll
            for (int mt = 0; mt < 4; mt++)
#pragma unroll
                for (int nt = 0; nt < 4; nt++)
                    mma16816(acc[mt][nt], a[mt], &b_[nt >> 1][(nt & 1) * 2]);
        }

        if (next) CP_WAIT0();
        __syncthreads();
        buf ^= 1;
    }

    const int g = lane >> 2, t4 = lane & 3;
#pragma unroll
    for (int mt = 0; mt < 4; mt++)
#pragma unroll
        for (int nt = 0; nt < 4; nt++) {
            int m0 = bm + wm + mt * 16 + g;
            int n0 = bn + wn + nt * 8 + t4 * 2;
            float b0 = __ldg(bias + n0), b1 = __ldg(bias + n0 + 1);
            store2(C, O, mode, m0,     n0, acc[mt][nt][0] + b0, acc[mt][nt][1] + b1);
            store2(C, O, mode, m0 + 8, n0, acc[mt][nt][2] + b0, acc[mt][nt][3] + b1);
        }
}

// ---------------------------------------------------------------------------
// Flash-style register-resident sparse attention.
// Block = (bh, r, qt): 64 queries i = 4*(q0+q)+r. 4 warps x 16 rows each,
// full 64-col tile width per warp. P stays in registers (C->A fragment map).
// Online softmax: m,l per row in registers, quad shuffles.
// K/V tiles double-buffered via cp.async; ONE syncthreads per tile.
// ---------------------------------------------------------------------------
#define KVS 72   // halfs per row (pad: 144B stride, 16B-mod-128 stagger)

__global__ void __launch_bounds__(128) attn_flash_kernel(
    const __half* __restrict__ qg, const __half* __restrict__ kg,
    const __half* __restrict__ vg, __half* __restrict__ out)
{
    __shared__ __half Qs[64 * KVS];
    __shared__ __half Kb[2][64 * KVS];
    __shared__ __half Vb[2][64 * KVS];

    const int tid = threadIdx.x, lane = tid & 31, w = tid >> 5;
    const int qt = 3 - (blockIdx.x >> 8);         // heavy tiles first
    const int bh = (blockIdx.x & 255) >> 2;
    const int r  = blockIdx.x & 3;
    const int q0 = qt * 64;
    const int ntiles = qt + 1;

    const int wq = w * 16;                        // warp's row base
    const int g = lane >> 2, t4 = lane & 3;
    const int lrow = lane & 15, lcol = (lane >> 4) << 3;
    const int bnrow = ((lane >> 4) << 3) + (lane & 7);
    const int bkoff = ((lane >> 3) & 1) << 3;

    const __half* kbase = kg + (((size_t)bh * 4 + r) * 256) * 64;
    const __half* vbase = vg + (((size_t)bh * 4 + r) * 256) * 64;

    // ---- load Q tile (sync) ----
#pragma unroll
    for (int j = 0; j < 4; j++) {
        int c = tid + 128 * j, row = c >> 3, co = (c & 7) * 8;
        int i = 4 * (q0 + row) + r;
        *(uint4*)&Qs[row * KVS + co] =
            *(const uint4*)(qg + ((size_t)bh * 1024 + i) * 64 + co);
    }
    __syncthreads();

    // ---- stage K0/V0 ----
    auto stage_kv = [&](int buf, int ut) {
#pragma unroll
        for (int j = 0; j < 4; j++) {
            int c = tid + 128 * j, row = c >> 3, co = (c & 7) * 8;
            cp_async16(&Kb[buf][row * KVS + co], kbase + (size_t)(ut * 64 + row) * 64 + co);
            cp_async16(&Vb[buf][row * KVS + co], vbase + (size_t)(ut * 64 + row) * 64 + co);
        }
    };
    stage_kv(0, 0);
    CP_COMMIT();

    // ---- Q fragments (registers, reused all tiles) ----
    uint32_t qf[4][4];
#pragma unroll
    for (int ks = 0; ks < 4; ks++)
        ldm_x4(qf[ks], &Qs[(wq + lrow) * KVS + ks * 16 + lcol]);

    // ---- locals pre-tile (j = i-1..i-3) ----
    const int i_g  = 4 * (q0 + wq + g) + r;
    const int i_g8 = i_g + 32;
    float m_g, m_g8, l_g, l_g8;
    float oacc[8][4];
#pragma unroll
    for (int nt = 0; nt < 8; nt++)
#pragma unroll
        for (int c = 0; c < 4; c++) oacc[nt][c] = 0.f;
    {
        float sg[3], sg8[3];
        const int nl_g = min(i_g, 3), nl_g8 = min(i_g8, 3);
#pragma unroll
        for (int l = 0; l < 3; l++) {
            float d0 = 0.f, d1 = 0.f;
            int jg = i_g - 1 - l, jg8 = i_g8 - 1 - l;
            if (l < nl_g) {
                const __half* kp = kg + ((((size_t)bh * 4 + (jg & 3)) * 256 + (jg >> 2)) * 64);
#pragma unroll
                for (int d = 0; d < 16; d += 2) {
                    __half2 a = *(const __half2*)&Qs[(wq + g) * KVS + t4 * 16 + d];
                    __half2 b = *(const __half2*)(kp + t4 * 16 + d);
                    d0 += __half2float(a.x) * __half2float(b.x)
                        + __half2float(a.y) * __half2float(b.y);
                }
            }
            if (l < nl_g8) {
                const __half* kp = kg + ((((size_t)bh * 4 + (jg8 & 3)) * 256 + (jg8 >> 2)) * 64);
#pragma unroll
                for (int d = 0; d < 16; d += 2) {
                    __half2 a = *(const __half2*)&Qs[(wq + g + 8) * KVS + t4 * 16 + d];
                    __half2 b = *(const __half2*)(kp + t4 * 16 + d);
                    d1 += __half2float(a.x) * __half2float(b.x)
                        + __half2float(a.y) * __half2float(b.y);
                }
            }
            d0 += __shfl_xor_sync(0xffffffffu, d0, 1);
            d0 += __shfl_xor_sync(0xffffffffu, d0, 2);
            d1 += __shfl_xor_sync(0xffffffffu, d1, 1);
            d1 += __shfl_xor_sync(0xffffffffu, d1, 2);
            sg[l]  = (l < nl_g)  ? d0 * 0.125f : -1e30f;
            sg8[l] = (l < nl_g8) ? d1 * 0.125f : -1e30f;
        }
        m_g  = fmaxf(fmaxf(sg[0], sg[1]), sg[2]);
        m_g8 = fmaxf(fmaxf(sg8[0], sg8[1]), sg8[2]);
        float p_g[3], p_g8[3];
        l_g = 0.f; l_g8 = 0.f;
#pragma unroll
        for (int l = 0; l < 3; l++) {
            p_g[l]  = (l < nl_g)  ? __expf(sg[l] - m_g)   : 0.f;
            p_g8[l] = (l < nl_g8) ? __expf(sg8[l] - m_g8) : 0.f;
            l_g += p_g[l]; l_g8 += p_g8[l];
        }
        // O init from locals' V rows
#pragma unroll
        for (int l = 0; l < 3; l++) {
            int jg = i_g - 1 - l, jg8 = i_g8 - 1 - l;
            if (l < nl_g) {
                const __half* vp = vg + ((((size_t)bh * 4 + (jg & 3)) * 256 + (jg >> 2)) * 64);
#pragma unroll
                for (int nt = 0; nt < 8; nt++) {
                    __half2 v2 = *(const __half2*)(vp + nt * 8 + t4 * 2);
                    oacc[nt][0] += p_g[l] * __half2float(v2.x);
                    oacc[nt][1] += p_g[l] * __half2float(v2.y);
                }
            }
            if (l < nl_g8) {
                const __half* vp = vg + ((((size_t)bh * 4 + (jg8 & 3)) * 256 + (jg8 >> 2)) * 64);
#pragma unroll
                for (int nt = 0; nt < 8; nt++) {
                    __half2 v2 = *(const __half2*)(vp + nt * 8 + t4 * 2);
                    oacc[nt][2] += p_g8[l] * __half2float(v2.x);
                    oacc[nt][3] += p_g8[l] * __half2float(v2.y);
                }
            }
        }
    }

    // ---- tile loop ----
    int buf = 0;
    for (int ut = 0; ut < ntiles; ut++) {
        CP_WAIT0();
        __syncthreads();
        if (ut + 1 < ntiles) {
            stage_kv(buf ^ 1, ut + 1);
            CP_COMMIT();
        }

        // S = Q K^T
        float acc[8][4];
#pragma unroll
        for (int nt = 0; nt < 8; nt++)
#pragma unroll
            for (int c = 0; c < 4; c++) acc[nt][c] = 0.f;
#pragma unroll
        for (int ks = 0; ks < 4; ks++)
#pragma unroll
            for (int nb = 0; nb < 4; nb++) {
                uint32_t bh4[4];
                ldm_x4(bh4, &Kb[buf][(nb * 16 + bnrow) * KVS + ks * 16 + bkoff]);
                mma16816(acc[nb * 2 + 0], qf[ks], &bh4[0]);
                mma16816(acc[nb * 2 + 1], qf[ks], &bh4[2]);
            }

        // scale + diagonal mask
        if (ut == qt) {
            const int lim_g = wq + g, lim_g8 = wq + g + 8;
#pragma unroll
            for (int nt = 0; nt < 8; nt++) {
                int u0 = nt * 8 + t4 * 2;
                acc[nt][0] = (u0     <= lim_g)  ? acc[nt][0] * 0.125f : -1e30f;
                acc[nt][1] = (u0 + 1 <= lim_g)  ? acc[nt][1] * 0.125f : -1e30f;
                acc[nt][2] = (u0     <= lim_g8) ? acc[nt][2] * 0.125f : -1e30f;
                acc[nt][3] = (u0 + 1 <= lim_g8) ? acc[nt][3] * 0.125f : -1e30f;
            }
        } else {
#pragma unroll
            for (int nt = 0; nt < 8; nt++)
#pragma unroll
                for (int c = 0; c < 4; c++) acc[nt][c] *= 0.125f;
        }

        // online softmax update
        float tm_g = -1e30f, tm_g8 = -1e30f;
#pragma unroll
        for (int nt = 0; nt < 8; nt++) {
            tm_g  = fmaxf(tm_g,  fmaxf(acc[nt][0], acc[nt][1]));
            tm_g8 = fmaxf(tm_g8, fmaxf(acc[nt][2], acc[nt][3]));
        }
        tm_g  = fmaxf(tm_g,  __shfl_xor_sync(0xffffffffu, tm_g, 1));
        tm_g  = fmaxf(tm_g,  __shfl_xor_sync(0xffffffffu, tm_g, 2));
        tm_g8 = fmaxf(tm_g8, __shfl_xor_sync(0xffffffffu, tm_g8, 1));
        tm_g8 = fmaxf(tm_g8, __shfl_xor_sync(0xffffffffu, tm_g8, 2));

        float mn_g = fmaxf(m_g, tm_g), mn_g8 = fmaxf(m_g8, tm_g8);
        float al_g = __expf(m_g - mn_g), al_g8 = __expf(m_g8 - mn_g8);
        m_g = mn_g; m_g8 = mn_g8;

        float ps_g = 0.f, ps_g8 = 0.f;
#pragma unroll
        for (int nt = 0; nt < 8; nt++) {
            float p0 = __expf(acc[nt][0] - mn_g);
            float p1 = __expf(acc[nt][1] - mn_g);
            float p2 = __expf(acc[nt][2] - mn_g8);
            float p3 = __expf(acc[nt][3] - mn_g8);
            acc[nt][0] = p0; acc[nt][1] = p1; acc[nt][2] = p2; acc[nt][3] = p3;
            ps_g += p0 + p1; ps_g8 += p2 + p3;
        }
        ps_g  += __shfl_xor_sync(0xffffffffu, ps_g, 1);
        ps_g  += __shfl_xor_sync(0xffffffffu, ps_g, 2);
        ps_g8 += __shfl_xor_sync(0xffffffffu, ps_g8, 1);
        ps_g8 += __shfl_xor_sync(0xffffffffu, ps_g8, 2);
        l_g = l_g * al_g + ps_g;
        l_g8 = l_g8 * al_g8 + ps_g8;
#pragma unroll
        for (int nt = 0; nt < 8; nt++) {
            oacc[nt][0] *= al_g;  oacc[nt][1] *= al_g;
            oacc[nt][2] *= al_g8; oacc[nt][3] *= al_g8;
        }

        // PV: P fragments straight from registers
#pragma unroll
        for (int ks = 0; ks < 4; ks++) {
            uint32_t pa[4];
            pa[0] = packh2(acc[2 * ks][0],     acc[2 * ks][1]);
            pa[1] = packh2(acc[2 * ks][2],     acc[2 * ks][3]);
            pa[2] = packh2(acc[2 * ks + 1][0], acc[2 * ks + 1][1]);
            pa[3] = packh2(acc[2 * ks + 1][2], acc[2 * ks + 1][3]);
#pragma unroll
            for (int nb = 0; nb < 4; nb++) {
                uint32_t vh4[4];
                ldm_x4_t(vh4, &Vb[buf][(ks * 16 + lrow) * KVS + nb * 16 + lcol]);
                mma16816(oacc[nb * 2 + 0], pa, &vh4[0]);
                mma16816(oacc[nb * 2 + 1], pa, &vh4[2]);
            }
        }
        buf ^= 1;
    }

    // ---- normalize, stage into smem (reuse Qs), coalesced store ----
    __syncthreads();
    {
        float inv_g = 1.0f / l_g, inv_g8 = 1.0f / l_g8;
#pragma unroll
        for (int nt = 0; nt < 8; nt++) {
            *(__half2*)&Qs[(wq + g) * KVS + nt * 8 + t4 * 2] =
                __floats2half2_rn(oacc[nt][0] * inv_g, oacc[nt][1] * inv_g);
            *(__half2*)&Qs[(wq + g + 8) * KVS + nt * 8 + t4 * 2] =
                __floats2half2_rn(oacc[nt][2] * inv_g8, oacc[nt][3] * inv_g8);
        }
    }
    __syncthreads();
    {
        int bb = bh >> 4, h = bh & 15;
#pragma unroll
        for (int j = 0; j < 4; j++) {
            int c = tid + 128 * j, row = c >> 3, co = (c & 7) * 8;
            int i = 4 * (q0 + row) + r;
            *(uint4*)(out + ((size_t)(bb * 1024 + i)) * 1024 + h * 64 + co) =
                *(const uint4*)&Qs[row * KVS + co];
        }
    }
}

// ---------------------------------------------------------------------------
extern "C" void kernel_launch(void* const* d_in, const int* in_sizes, int n_in,
                              void* d_out, int out_size)
{
    const float* Q  = (const float*)d_in[0];
    const float* K  = (const float*)d_in[1];
    const float* V  = (const float*)d_in[2];
    const float* Wq = (const float*)d_in[3];
    const float* bq = (const float*)d_in[4];
    const float* Wk = (const float*)d_in[5];
    const float* bk = (const float*)d_in[6];
    const float* Wv = (const float*)d_in[7];
    const float* bv = (const float*)d_in[8];
    const float* Wo = (const float*)d_in[9];
    const float* bo = (const float*)d_in[10];
    float* out = (float*)d_out;

    __half *pqin, *pkin, *pvin, *pw, *pq, *pk, *pv, *pah;
    cudaGetSymbolAddress((void**)&pqin, g_qin);
    cudaGetSymbolAddress((void**)&pkin, g_kin);
    cudaGetSymbolAddress((void**)&pvin, g_vin);
    cudaGetSymbolAddress((void**)&pw, g_w);
    cudaGetSymbolAddress((void**)&pq, g_q);
    cudaGetSymbolAddress((void**)&pk, g_k);
    cudaGetSymbolAddress((void**)&pv, g_v);
    cudaGetSymbolAddress((void**)&pah, g_attn);

    cudaFuncSetAttribute(gemm_cp_kernel,
                         cudaFuncAttributeMaxDynamicSharedMemorySize, GEMM_SMEM);

    conv3_kernel<<<dim3(4096, 3), 256>>>(Q, K, V, pqin, pkin, pvin);
    conv4_kernel<<<dim3(1024, 4), 256>>>(Wq, Wk, Wv, Wo, pw);

    dim3 gg(8, 32);
    dim3 tb(256);

    gemm_cp_kernel<<<gg, tb, GEMM_SMEM>>>(pqin, pw,               bq, nullptr, pq, 1);
    gemm_cp_kernel<<<gg, tb, GEMM_SMEM>>>(pkin, pw + 1 * DD * DD, bk, nullptr, pk, 2);
    gemm_cp_kernel<<<gg, tb, GEMM_SMEM>>>(pvin, pw + 2 * DD * DD, bv, nullptr, pv, 2);

    attn_flash_kernel<<<1024, 128>>>(pq, pk, pv, pah);

    gemm_cp_kernel<<<gg, tb, GEMM_SMEM>>>(pah, pw + 3 * DD * DD, bo, out, nullptr, 0);
}

// round 9
// speedup vs baseline: 5.6917x; 1.0022x over previous
#include <cuda_runtime.h>
#include <cuda_fp16.h>
#include <cstdint>

#define BB 4
#define SS 1024
#define DD 1024
#define HH 16
#define DK 64
#define NEL (BB * HH * SS * DK)   // 4M

// Scratch (__device__ globals)
__device__ __half g_qin[NEL], g_kin[NEL], g_vin[NEL];   // fp16 input copies [B,S,D]
__device__ __half g_w[4 * DD * DD];                     // fp16 weights [k][n] (4 mats)
__device__ __half g_q[NEL];          // [bh][s][d]
__device__ __half g_k[NEL];          // [bh][r][u][d]
__device__ __half g_v[NEL];          // [bh][r][u][d]
__device__ __half g_attn[BB * SS * DD];                 // fp16 attention out [B,S,D]

// ---------------------------------------------------------------------------
__device__ __forceinline__ unsigned saddr(const void* p) {
    return (unsigned)__cvta_generic_to_shared(p);
}
__device__ __forceinline__ void ldm_x4(uint32_t* r, const void* p) {
    asm volatile("ldmatrix.sync.aligned.m8n8.x4.shared.b16 {%0,%1,%2,%3}, [%4];"
        : "=r"(r[0]), "=r"(r[1]), "=r"(r[2]), "=r"(r[3]) : "r"(saddr(p)));
}
__device__ __forceinline__ void ldm_x4_t(uint32_t* r, const void* p) {
    asm volatile("ldmatrix.sync.aligned.m8n8.x4.trans.shared.b16 {%0,%1,%2,%3}, [%4];"
        : "=r"(r[0]), "=r"(r[1]), "=r"(r[2]), "=r"(r[3]) : "r"(saddr(p)));
}
__device__ __forceinline__ void mma16816(float* c, const uint32_t* a, const uint32_t* b) {
    asm volatile("mma.sync.aligned.m16n8k16.row.col.f32.f16.f16.f32 "
        "{%0,%1,%2,%3},{%4,%5,%6,%7},{%8,%9},{%0,%1,%2,%3};"
        : "+f"(c[0]), "+f"(c[1]), "+f"(c[2]), "+f"(c[3])
        : "r"(a[0]), "r"(a[1]), "r"(a[2]), "r"(a[3]), "r"(b[0]), "r"(b[1]));
}
__device__ __forceinline__ void cp_async16(void* s, const void* g) {
    asm volatile("cp.async.cg.shared.global [%0], [%1], 16;"
        :: "r"(saddr(s)), "l"(g));
}
#define CP_COMMIT() asm volatile("cp.async.commit_group;" ::: "memory")
#define CP_WAIT(n)  asm volatile("cp.async.wait_group %0;" :: "n"(n) : "memory")

__device__ __forceinline__ uint32_t packh2(float a, float b) {
    __half2 p = __floats2half2_rn(a, b);
    return *(uint32_t*)&p;
}

// ---------------------------------------------------------------------------
// Prep: fp32 -> fp16, batched by blockIdx.y
// ---------------------------------------------------------------------------
__global__ void __launch_bounds__(256) conv3_kernel(
    const float* __restrict__ s0, const float* __restrict__ s1,
    const float* __restrict__ s2, __half* __restrict__ d0,
    __half* __restrict__ d1, __half* __restrict__ d2)
{
    const float* src = (blockIdx.y == 0) ? s0 : (blockIdx.y == 1) ? s1 : s2;
    __half* dst = (blockIdx.y == 0) ? d0 : (blockIdx.y == 1) ? d1 : d2;
    int i = blockIdx.x * 256 + threadIdx.x;
    float4 v = *(const float4*)(src + (size_t)i * 4);
    uint2 u; u.x = packh2(v.x, v.y); u.y = packh2(v.z, v.w);
    *(uint2*)(dst + (size_t)i * 4) = u;
}

__global__ void __launch_bounds__(256) conv4_kernel(
    const float* __restrict__ s0, const float* __restrict__ s1,
    const float* __restrict__ s2, const float* __restrict__ s3,
    __half* __restrict__ dst)
{
    const float* src = (blockIdx.y == 0) ? s0 : (blockIdx.y == 1) ? s1
                     : (blockIdx.y == 2) ? s2 : s3;
    __half* d = dst + (size_t)blockIdx.y * DD * DD;
    int i = blockIdx.x * 256 + threadIdx.x;
    float4 v = *(const float4*)(src + (size_t)i * 4);
    uint2 u; u.x = packh2(v.x, v.y); u.y = packh2(v.z, v.w);
    *(uint2*)(d + (size_t)i * 4) = u;
}

// ---------------------------------------------------------------------------
// fp16 GEMM body, 4-stage cp.async pipeline.
// C = A[4096,1024] @ W[1024,1024] + bias
// mode 0: fp32 C[m*1024+n]
// mode 1: fp16 O, idx = ((b*16+h)*1024+s)*64+d
// mode 2: fp16 O, idx = (((b*16+h)*4+(s&3))*256+(s>>2))*64+d
// ---------------------------------------------------------------------------
#define APAD 48
#define WPAD 144
#define A_SZ (128 * APAD)
#define W_SZ (32 * WPAD)
#define STAGES 4
#define GEMM_SMEM (STAGES * (A_SZ + W_SZ) * 2)   // 86016 bytes

__device__ __forceinline__ void store2(
    float* __restrict__ C, __half* __restrict__ O, int mode,
    int m, int n, float v0, float v1)
{
    if (mode == 0) {
        *(float2*)(C + (size_t)m * 1024 + n) = make_float2(v0, v1);
        return;
    }
    int b = m >> 10, s = m & 1023, h = n >> 6, d = n & 63;
    size_t idx;
    if (mode == 1) idx = (((size_t)(b * 16 + h)) * 1024 + s) * 64 + d;
    else           idx = ((((size_t)(b * 16 + h)) * 4 + (s & 3)) * 256 + (s >> 2)) * 64 + d;
    __half2 p = __floats2half2_rn(v0, v1);
    *(__half2*)(O + idx) = p;
}

__device__ __forceinline__ void gemm_body(
    const __half* __restrict__ A, const __half* __restrict__ Wm,
    const float* __restrict__ bias, float* __restrict__ C,
    __half* __restrict__ O, int mode, __half* smem)
{
    __half* sA = smem;                       // [STAGES][128][APAD]
    __half* sW = smem + STAGES * A_SZ;       // [STAGES][32][WPAD]

    const int tid = threadIdx.x;
    const int bm = blockIdx.y * 128, bn = blockIdx.x * 128;
    const int w = tid >> 5, lane = tid & 31;
    const int wm = (w & 1) * 64, wn = (w >> 1) * 32;
    const int lrow = lane & 15, lcol = (lane >> 4) << 3;

    const int ac0 = tid * 2;
    const int ar0 = ac0 >> 2,  aco0 = (ac0 & 3) * 8;
    const int ar1 = (ac0 + 1) >> 2, aco1 = ((ac0 + 1) & 3) * 8;
    const int wr0 = ac0 >> 4,  wco0 = (ac0 & 15) * 8;
    const int wr1 = (ac0 + 1) >> 4, wco1 = ((ac0 + 1) & 15) * 8;

    float acc[4][4][4];
#pragma unroll
    for (int i = 0; i < 4; i++)
#pragma unroll
        for (int j = 0; j < 4; j++)
#pragma unroll
            for (int t = 0; t < 4; t++) acc[i][j][t] = 0.f;

    auto stage = [&](int buf, int k0) {
        cp_async16(&sA[buf * A_SZ + ar0 * APAD + aco0],
                   A + (size_t)(bm + ar0) * 1024 + k0 + aco0);
        cp_async16(&sA[buf * A_SZ + ar1 * APAD + aco1],
                   A + (size_t)(bm + ar1) * 1024 + k0 + aco1);
        cp_async16(&sW[buf * W_SZ + wr0 * WPAD + wco0],
                   Wm + (size_t)(k0 + wr0) * 1024 + bn + wco0);
        cp_async16(&sW[buf * W_SZ + wr1 * WPAD + wco1],
                   Wm + (size_t)(k0 + wr1) * 1024 + bn + wco1);
    };

    // prologue: stage tiles 0..2
#pragma unroll
    for (int s = 0; s < STAGES - 1; s++) {
        stage(s, s * 32);
        CP_COMMIT();
    }

    for (int kt = 0; kt < 32; kt++) {
        CP_WAIT(STAGES - 2);       // oldest outstanding tile (kt) has landed
        __syncthreads();           // all warps done with tile kt-1 (= staging target)

        int nk = kt + STAGES - 1;
        if (nk < 32) stage(nk & (STAGES - 1), nk * 32);
        CP_COMMIT();

        const __half* cA = sA + (kt & (STAGES - 1)) * A_SZ;
        const __half* cW = sW + (kt & (STAGES - 1)) * W_SZ;

#pragma unroll
        for (int kk = 0; kk < 32; kk += 16) {
            uint32_t a[4][4], b_[2][4];
#pragma unroll
            for (int mt = 0; mt < 4; mt++)
                ldm_x4(a[mt], &cA[(wm + mt * 16 + lrow) * APAD + kk + lcol]);
#pragma unroll
            for (int np = 0; np < 2; np++)
                ldm_x4_t(b_[np], &cW[(kk + lrow) * WPAD + wn + np * 16 + lcol]);
#pragma unroll
            for (int mt = 0; mt < 4; mt++)
#pragma unroll
                for (int nt = 0; nt < 4; nt++)
                    mma16816(acc[mt][nt], a[mt], &b_[nt >> 1][(nt & 1) * 2]);
        }
    }

    const int g = lane >> 2, t4 = lane & 3;
#pragma unroll
    for (int mt = 0; mt < 4; mt++)
#pragma unroll
        for (int nt = 0; nt < 4; nt++) {
            int m0 = bm + wm + mt * 16 + g;
            int n0 = bn + wn + nt * 8 + t4 * 2;
            float b0 = __ldg(bias + n0), b1 = __ldg(bias + n0 + 1);
            store2(C, O, mode, m0,     n0, acc[mt][nt][0] + b0, acc[mt][nt][1] + b1);
            store2(C, O, mode, m0 + 8, n0, acc[mt][nt][2] + b0, acc[mt][nt][3] + b1);
        }
}

// Fused Q/K/V projection: blockIdx.z selects input/weight/bias/output.
__global__ void __launch_bounds__(256) gemm_qkv_kernel(
    const __half* __restrict__ Aq, const __half* __restrict__ Ak,
    const __half* __restrict__ Av, const __half* __restrict__ Wall,
    const float* __restrict__ bq, const float* __restrict__ bk,
    const float* __restrict__ bv,
    __half* __restrict__ Oq, __half* __restrict__ Ok, __half* __restrict__ Ov)
{
    extern __shared__ __half smem[];
    int z = blockIdx.z;
    const __half* A = (z == 0) ? Aq : (z == 1) ? Ak : Av;
    const float* bias = (z == 0) ? bq : (z == 1) ? bk : bv;
    __half* O = (z == 0) ? Oq : (z == 1) ? Ok : Ov;
    gemm_body(A, Wall + (size_t)z * DD * DD, bias, nullptr, O,
              (z == 0) ? 1 : 2, smem);
}

// Output projection (fp32 out).
__global__ void __launch_bounds__(256) gemm_o_kernel(
    const __half* __restrict__ A, const __half* __restrict__ Wm,
    const float* __restrict__ bias, float* __restrict__ C)
{
    extern __shared__ __half smem[];
    gemm_body(A, Wm, bias, C, nullptr, 0, smem);
}

// ---------------------------------------------------------------------------
// Flash-style register-resident sparse attention (unchanged from R8).
// ---------------------------------------------------------------------------
#define KVS 72

__global__ void __launch_bounds__(128) attn_flash_kernel(
    const __half* __restrict__ qg, const __half* __restrict__ kg,
    const __half* __restrict__ vg, __half* __restrict__ out)
{
    __shared__ __half Qs[64 * KVS];
    __shared__ __half Kb[2][64 * KVS];
    __shared__ __half Vb[2][64 * KVS];

    const int tid = threadIdx.x, lane = tid & 31, w = tid >> 5;
    const int qt = 3 - (blockIdx.x >> 8);
    const int bh = (blockIdx.x & 255) >> 2;
    const int r  = blockIdx.x & 3;
    const int q0 = qt * 64;
    const int ntiles = qt + 1;

    const int wq = w * 16;
    const int g = lane >> 2, t4 = lane & 3;
    const int lrow = lane & 15, lcol = (lane >> 4) << 3;
    const int bnrow = ((lane >> 4) << 3) + (lane & 7);
    const int bkoff = ((lane >> 3) & 1) << 3;

    const __half* kbase = kg + (((size_t)bh * 4 + r) * 256) * 64;
    const __half* vbase = vg + (((size_t)bh * 4 + r) * 256) * 64;

#pragma unroll
    for (int j = 0; j < 4; j++) {
        int c = tid + 128 * j, row = c >> 3, co = (c & 7) * 8;
        int i = 4 * (q0 + row) + r;
        *(uint4*)&Qs[row * KVS + co] =
            *(const uint4*)(qg + ((size_t)bh * 1024 + i) * 64 + co);
    }
    __syncthreads();

    auto stage_kv = [&](int buf, int ut) {
#pragma unroll
        for (int j = 0; j < 4; j++) {
            int c = tid + 128 * j, row = c >> 3, co = (c & 7) * 8;
            cp_async16(&Kb[buf][row * KVS + co], kbase + (size_t)(ut * 64 + row) * 64 + co);
            cp_async16(&Vb[buf][row * KVS + co], vbase + (size_t)(ut * 64 + row) * 64 + co);
        }
    };
    stage_kv(0, 0);
    CP_COMMIT();

    uint32_t qf[4][4];
#pragma unroll
    for (int ks = 0; ks < 4; ks++)
        ldm_x4(qf[ks], &Qs[(wq + lrow) * KVS + ks * 16 + lcol]);

    const int i_g  = 4 * (q0 + wq + g) + r;
    const int i_g8 = i_g + 32;
    float m_g, m_g8, l_g, l_g8;
    float oacc[8][4];
#pragma unroll
    for (int nt = 0; nt < 8; nt++)
#pragma unroll
        for (int c = 0; c < 4; c++) oacc[nt][c] = 0.f;
    {
        float sg[3], sg8[3];
        const int nl_g = min(i_g, 3), nl_g8 = min(i_g8, 3);
#pragma unroll
        for (int l = 0; l < 3; l++) {
            float d0 = 0.f, d1 = 0.f;
            int jg = i_g - 1 - l, jg8 = i_g8 - 1 - l;
            if (l < nl_g) {
                const __half* kp = kg + ((((size_t)bh * 4 + (jg & 3)) * 256 + (jg >> 2)) * 64);
#pragma unroll
                for (int d = 0; d < 16; d += 2) {
                    __half2 a = *(const __half2*)&Qs[(wq + g) * KVS + t4 * 16 + d];
                    __half2 b = *(const __half2*)(kp + t4 * 16 + d);
                    d0 += __half2float(a.x) * __half2float(b.x)
                        + __half2float(a.y) * __half2float(b.y);
                }
            }
            if (l < nl_g8) {
                const __half* kp = kg + ((((size_t)bh * 4 + (jg8 & 3)) * 256 + (jg8 >> 2)) * 64);
#pragma unroll
                for (int d = 0; d < 16; d += 2) {
                    __half2 a = *(const __half2*)&Qs[(wq + g + 8) * KVS + t4 * 16 + d];
                    __half2 b = *(const __half2*)(kp + t4 * 16 + d);
                    d1 += __half2float(a.x) * __half2float(b.x)
                        + __half2float(a.y) * __half2float(b.y);
                }
            }
            d0 += __shfl_xor_sync(0xffffffffu, d0, 1);
            d0 += __shfl_xor_sync(0xffffffffu, d0, 2);
            d1 += __shfl_xor_sync(0xffffffffu, d1, 1);
            d1 += __shfl_xor_sync(0xffffffffu, d1, 2);
            sg[l]  = (l < nl_g)  ? d0 * 0.125f : -1e30f;
            sg8[l] = (l < nl_g8) ? d1 * 0.125f : -1e30f;
        }
        m_g  = fmaxf(fmaxf(sg[0], sg[1]), sg[2]);
        m_g8 = fmaxf(fmaxf(sg8[0], sg8[1]), sg8[2]);
        float p_g[3], p_g8[3];
        l_g = 0.f; l_g8 = 0.f;
#pragma unroll
        for (int l = 0; l < 3; l++) {
            p_g[l]  = (l < nl_g)  ? __expf(sg[l] - m_g)   : 0.f;
            p_g8[l] = (l < nl_g8) ? __expf(sg8[l] - m_g8) : 0.f;
            l_g += p_g[l]; l_g8 += p_g8[l];
        }
#pragma unroll
        for (int l = 0; l < 3; l++) {
            int jg = i_g - 1 - l, jg8 = i_g8 - 1 - l;
            if (l < nl_g) {
                const __half* vp = vg + ((((size_t)bh * 4 + (jg & 3)) * 256 + (jg >> 2)) * 64);
#pragma unroll
                for (int nt = 0; nt < 8; nt++) {
                    __half2 v2 = *(const __half2*)(vp + nt * 8 + t4 * 2);
                    oacc[nt][0] += p_g[l] * __half2float(v2.x);
                    oacc[nt][1] += p_g[l] * __half2float(v2.y);
                }
            }
            if (l < nl_g8) {
                const __half* vp = vg + ((((size_t)bh * 4 + (jg8 & 3)) * 256 + (jg8 >> 2)) * 64);
#pragma unroll
                for (int nt = 0; nt < 8; nt++) {
                    __half2 v2 = *(const __half2*)(vp + nt * 8 + t4 * 2);
                    oacc[nt][2] += p_g8[l] * __half2float(v2.x);
                    oacc[nt][3] += p_g8[l] * __half2float(v2.y);
                }
            }
        }
    }

    int buf = 0;
    for (int ut = 0; ut < ntiles; ut++) {
        CP_WAIT(0);
        __syncthreads();
        if (ut + 1 < ntiles) {
            stage_kv(buf ^ 1, ut + 1);
            CP_COMMIT();
        }

        float acc[8][4];
#pragma unroll
        for (int nt = 0; nt < 8; nt++)
#pragma unroll
            for (int c = 0; c < 4; c++) acc[nt][c] = 0.f;
#pragma unroll
        for (int ks = 0; ks < 4; ks++)
#pragma unroll
            for (int nb = 0; nb < 4; nb++) {
                uint32_t bh4[4];
                ldm_x4(bh4, &Kb[buf][(nb * 16 + bnrow) * KVS + ks * 16 + bkoff]);
                mma16816(acc[nb * 2 + 0], qf[ks], &bh4[0]);
                mma16816(acc[nb * 2 + 1], qf[ks], &bh4[2]);
            }

        if (ut == qt) {
            const int lim_g = wq + g, lim_g8 = wq + g + 8;
#pragma unroll
            for (int nt = 0; nt < 8; nt++) {
                int u0 = nt * 8 + t4 * 2;
                acc[nt][0] = (u0     <= lim_g)  ? acc[nt][0] * 0.125f : -1e30f;
                acc[nt][1] = (u0 + 1 <= lim_g)  ? acc[nt][1] * 0.125f : -1e30f;
                acc[nt][2] = (u0     <= lim_g8) ? acc[nt][2] * 0.125f : -1e30f;
                acc[nt][3] = (u0 + 1 <= lim_g8) ? acc[nt][3] * 0.125f : -1e30f;
            }
        } else {
#pragma unroll
            for (int nt = 0; nt < 8; nt++)
#pragma unroll
                for (int c = 0; c < 4; c++) acc[nt][c] *= 0.125f;
        }

        float tm_g = -1e30f, tm_g8 = -1e30f;
#pragma unroll
        for (int nt = 0; nt < 8; nt++) {
            tm_g  = fmaxf(tm_g,  fmaxf(acc[nt][0], acc[nt][1]));
            tm_g8 = fmaxf(tm_g8, fmaxf(acc[nt][2], acc[nt][3]));
        }
        tm_g  = fmaxf(tm_g,  __shfl_xor_sync(0xffffffffu, tm_g, 1));
        tm_g  = fmaxf(tm_g,  __shfl_xor_sync(0xffffffffu, tm_g, 2));
        tm_g8 = fmaxf(tm_g8, __shfl_xor_sync(0xffffffffu, tm_g8, 1));
        tm_g8 = fmaxf(tm_g8, __shfl_xor_sync(0xffffffffu, tm_g8, 2));

        float mn_g = fmaxf(m_g, tm_g), mn_g8 = fmaxf(m_g8, tm_g8);
        float al_g = __expf(m_g - mn_g), al_g8 = __expf(m_g8 - mn_g8);
        m_g = mn_g; m_g8 = mn_g8;

        float ps_g = 0.f, ps_g8 = 0.f;
#pragma unroll
        for (int nt = 0; nt < 8; nt++) {
            float p0 = __expf(acc[nt][0] - mn_g);
            float p1 = __expf(acc[nt][1] - mn_g);
            float p2 = __expf(acc[nt][2] - mn_g8);
            float p3 = __expf(acc[nt][3] - mn_g8);
            acc[nt][0] = p0; acc[nt][1] = p1; acc[nt][2] = p2; acc[nt][3] = p3;
            ps_g += p0 + p1; ps_g8 += p2 + p3;
        }
        ps_g  += __shfl_xor_sync(0xffffffffu, ps_g, 1);
        ps_g  += __shfl_xor_sync(0xffffffffu, ps_g, 2);
        ps_g8 += __shfl_xor_sync(0xffffffffu, ps_g8, 1);
        ps_g8 += __shfl_xor_sync(0xffffffffu, ps_g8, 2);
        l_g = l_g * al_g + ps_g;
        l_g8 = l_g8 * al_g8 + ps_g8;
#pragma unroll
        for (int nt = 0; nt < 8; nt++) {
            oacc[nt][0] *= al_g;  oacc[nt][1] *= al_g;
            oacc[nt][2] *= al_g8; oacc[nt][3] *= al_g8;
        }

#pragma unroll
        for (int ks = 0; ks < 4; ks++) {
            uint32_t pa[4];
            pa[0] = packh2(acc[2 * ks][0],     acc[2 * ks][1]);
            pa[1] = packh2(acc[2 * ks][2],     acc[2 * ks][3]);
            pa[2] = packh2(acc[2 * ks + 1][0], acc[2 * ks + 1][1]);
            pa[3] = packh2(acc[2 * ks + 1][2], acc[2 * ks + 1][3]);
#pragma unroll
            for (int nb = 0; nb < 4; nb++) {
                uint32_t vh4[4];
                ldm_x4_t(vh4, &Vb[buf][(ks * 16 + lrow) * KVS + nb * 16 + lcol]);
                mma16816(oacc[nb * 2 + 0], pa, &vh4[0]);
                mma16816(oacc[nb * 2 + 1], pa, &vh4[2]);
            }
        }
        buf ^= 1;
    }

    __syncthreads();
    {
        float inv_g = 1.0f / l_g, inv_g8 = 1.0f / l_g8;
#pragma unroll
        for (int nt = 0; nt < 8; nt++) {
            *(__half2*)&Qs[(wq + g) * KVS + nt * 8 + t4 * 2] =
                __floats2half2_rn(oacc[nt][0] * inv_g, oacc[nt][1] * inv_g);
            *(__half2*)&Qs[(wq + g + 8) * KVS + nt * 8 + t4 * 2] =
                __floats2half2_rn(oacc[nt][2] * inv_g8, oacc[nt][3] * inv_g8);
        }
    }
    __syncthreads();
    {
        int bb = bh >> 4, h = bh & 15;
#pragma unroll
        for (int j = 0; j < 4; j++) {
            int c = tid + 128 * j, row = c >> 3, co = (c & 7) * 8;
            int i = 4 * (q0 + row) + r;
            *(uint4*)(out + ((size_t)(bb * 1024 + i)) * 1024 + h * 64 + co) =
                *(const uint4*)&Qs[row * KVS + co];
        }
    }
}

// ---------------------------------------------------------------------------
extern "C" void kernel_launch(void* const* d_in, const int* in_sizes, int n_in,
                              void* d_out, int out_size)
{
    const float* Q  = (const float*)d_in[0];
    const float* K  = (const float*)d_in[1];
    const float* V  = (const float*)d_in[2];
    const float* Wq = (const float*)d_in[3];
    const float* bq = (const float*)d_in[4];
    const float* Wk = (const float*)d_in[5];
    const float* bk = (const float*)d_in[6];
    const float* Wv = (const float*)d_in[7];
    const float* bv = (const float*)d_in[8];
    const float* Wo = (const float*)d_in[9];
    const float* bo = (const float*)d_in[10];
    float* out = (float*)d_out;

    __half *pqin, *pkin, *pvin, *pw, *pq, *pk, *pv, *pah;
    cudaGetSymbolAddress((void**)&pqin, g_qin);
    cudaGetSymbolAddress((void**)&pkin, g_kin);
    cudaGetSymbolAddress((void**)&pvin, g_vin);
    cudaGetSymbolAddress((void**)&pw, g_w);
    cudaGetSymbolAddress((void**)&pq, g_q);
    cudaGetSymbolAddress((void**)&pk, g_k);
    cudaGetSymbolAddress((void**)&pv, g_v);
    cudaGetSymbolAddress((void**)&pah, g_attn);

    cudaFuncSetAttribute(gemm_qkv_kernel,
                         cudaFuncAttributeMaxDynamicSharedMemorySize, GEMM_SMEM);
    cudaFuncSetAttribute(gemm_o_kernel,
                         cudaFuncAttributeMaxDynamicSharedMemorySize, GEMM_SMEM);

    conv3_kernel<<<dim3(4096, 3), 256>>>(Q, K, V, pqin, pkin, pvin);
    conv4_kernel<<<dim3(1024, 4), 256>>>(Wq, Wk, Wv, Wo, pw);

    gemm_qkv_kernel<<<dim3(8, 32, 3), 256, GEMM_SMEM>>>(
        pqin, pkin, pvin, pw, bq, bk, bv, pq, pk, pv);

    attn_flash_kernel<<<1024, 128>>>(pq, pk, pv, pah);

    gemm_o_kernel<<<dim3(8, 32), 256, GEMM_SMEM>>>(
        pah, pw + 3 * (size_t)DD * DD, bo, out);
}

// round 10
// speedup vs baseline: 6.9537x; 1.2217x over previous
#include <cuda_runtime.h>
#include <cuda_fp16.h>
#include <cstdint>

#define BB 4
#define SS 1024
#define DD 1024
#define HH 16
#define DK 64
#define NEL (BB * HH * SS * DK)   // 4M

// Scratch (__device__ globals)
__device__ __half g_qin[NEL], g_kin[NEL], g_vin[NEL];   // fp16 input copies [B,S,D]
__device__ __half g_w[4 * DD * DD];                     // fp16 weights [k][n] (4 mats)
__device__ __half g_q[NEL];          // [bh][s][d]
__device__ __half g_k[NEL];          // [bh][r][u][d]
__device__ __half g_v[NEL];          // [bh][r][u][d]
__device__ __half g_attn[BB * SS * DD];                 // fp16 attention out [B,S,D]

// ---------------------------------------------------------------------------
__device__ __forceinline__ unsigned saddr(const void* p) {
    return (unsigned)__cvta_generic_to_shared(p);
}
__device__ __forceinline__ void ldm_x4(uint32_t* r, const void* p) {
    asm volatile("ldmatrix.sync.aligned.m8n8.x4.shared.b16 {%0,%1,%2,%3}, [%4];"
        : "=r"(r[0]), "=r"(r[1]), "=r"(r[2]), "=r"(r[3]) : "r"(saddr(p)));
}
__device__ __forceinline__ void ldm_x4_t(uint32_t* r, const void* p) {
    asm volatile("ldmatrix.sync.aligned.m8n8.x4.trans.shared.b16 {%0,%1,%2,%3}, [%4];"
        : "=r"(r[0]), "=r"(r[1]), "=r"(r[2]), "=r"(r[3]) : "r"(saddr(p)));
}
__device__ __forceinline__ void mma16816(float* c, const uint32_t* a, const uint32_t* b) {
    asm volatile("mma.sync.aligned.m16n8k16.row.col.f32.f16.f16.f32 "
        "{%0,%1,%2,%3},{%4,%5,%6,%7},{%8,%9},{%0,%1,%2,%3};"
        : "+f"(c[0]), "+f"(c[1]), "+f"(c[2]), "+f"(c[3])
        : "r"(a[0]), "r"(a[1]), "r"(a[2]), "r"(a[3]), "r"(b[0]), "r"(b[1]));
}
__device__ __forceinline__ void cp_async16(void* s, const void* g) {
    asm volatile("cp.async.cg.shared.global [%0], [%1], 16;"
        :: "r"(saddr(s)), "l"(g));
}
#define CP_COMMIT() asm volatile("cp.async.commit_group;" ::: "memory")
#define CP_WAIT(n)  asm volatile("cp.async.wait_group %0;" :: "n"(n) : "memory")

__device__ __forceinline__ uint32_t packh2(float a, float b) {
    __half2 p = __floats2half2_rn(a, b);
    return *(uint32_t*)&p;
}

// ---------------------------------------------------------------------------
// Fused prep: all fp32->fp16 conversions in ONE launch.
// Regions (blocks of 256 thr, 4 elems/thr):
//   [0,4096) Q, [4096,8192) K, [8192,12288) V, [12288,16384) weights (4x1024)
// ---------------------------------------------------------------------------
__global__ void __launch_bounds__(256) convall_kernel(
    const float* __restrict__ Q, const float* __restrict__ K,
    const float* __restrict__ V,
    const float* __restrict__ W0, const float* __restrict__ W1,
    const float* __restrict__ W2, const float* __restrict__ W3,
    __half* __restrict__ dq, __half* __restrict__ dk, __half* __restrict__ dv,
    __half* __restrict__ dw)
{
    int b = blockIdx.x;
    const float* src;
    __half* dst;
    int lb;
    if (b < 4096)       { src = Q; dst = dq; lb = b; }
    else if (b < 8192)  { src = K; dst = dk; lb = b - 4096; }
    else if (b < 12288) { src = V; dst = dv; lb = b - 8192; }
    else {
        int wb = b - 12288;           // 0..4095
        int wz = wb >> 10;            // which weight
        src = (wz == 0) ? W0 : (wz == 1) ? W1 : (wz == 2) ? W2 : W3;
        dst = dw + (size_t)wz * DD * DD;
        lb = wb & 1023;
    }
    size_t i = (size_t)lb * 256 + threadIdx.x;
    float4 v = *(const float4*)(src + i * 4);
    uint2 u; u.x = packh2(v.x, v.y); u.y = packh2(v.z, v.w);
    *(uint2*)(dst + i * 4) = u;
}

// ---------------------------------------------------------------------------
// fp16 GEMM body, BK=64, 3-stage cp.async pipeline, 16 k-iterations.
// C = A[4096,1024] @ W[1024,1024] + bias
// mode 0: fp32 C[m*1024+n]
// mode 1: fp16 O, idx = ((b*16+h)*1024+s)*64+d
// mode 2: fp16 O, idx = (((b*16+h)*4+(s&3))*256+(s>>2))*64+d
// ---------------------------------------------------------------------------
#define APAD 72              // halfs per A row (144B, 16B-aligned)
#define WPAD 144             // halfs per W row (288B)
#define A_SZ (128 * APAD)    // halfs per A stage
#define W_SZ (64 * WPAD)     // halfs per W stage
#define STAGES 3
#define GEMM_SMEM (STAGES * (A_SZ + W_SZ) * 2)   // 110,592 bytes

__device__ __forceinline__ void store2(
    float* __restrict__ C, __half* __restrict__ O, int mode,
    int m, int n, float v0, float v1)
{
    if (mode == 0) {
        *(float2*)(C + (size_t)m * 1024 + n) = make_float2(v0, v1);
        return;
    }
    int b = m >> 10, s = m & 1023, h = n >> 6, d = n & 63;
    size_t idx;
    if (mode == 1) idx = (((size_t)(b * 16 + h)) * 1024 + s) * 64 + d;
    else           idx = ((((size_t)(b * 16 + h)) * 4 + (s & 3)) * 256 + (s >> 2)) * 64 + d;
    __half2 p = __floats2half2_rn(v0, v1);
    *(__half2*)(O + idx) = p;
}

__device__ __forceinline__ void gemm_body(
    const __half* __restrict__ A, const __half* __restrict__ Wm,
    const float* __restrict__ bias, float* __restrict__ C,
    __half* __restrict__ O, int mode, __half* smem)
{
    __half* sA = smem;                       // [STAGES][128][APAD]
    __half* sW = smem + STAGES * A_SZ;       // [STAGES][64][WPAD]

    const int tid = threadIdx.x;
    const int bm = blockIdx.y * 128, bn = blockIdx.x * 128;
    const int w = tid >> 5, lane = tid & 31;
    const int wm = (w & 1) * 64, wn = (w >> 1) * 32;
    const int lrow = lane & 15, lcol = (lane >> 4) << 3;

    float acc[4][4][4];
#pragma unroll
    for (int i = 0; i < 4; i++)
#pragma unroll
        for (int j = 0; j < 4; j++)
#pragma unroll
            for (int t = 0; t < 4; t++) acc[i][j][t] = 0.f;

    // staging: A tile 128x64 halfs = 1024 16B-chunks; W tile 64x128 = 1024 chunks
    auto stage = [&](int buf, int k0) {
#pragma unroll
        for (int j = 0; j < 4; j++) {
            int c = tid + 256 * j;
            int arow = c >> 3, aco = (c & 7) * 8;
            cp_async16(&sA[buf * A_SZ + arow * APAD + aco],
                       A + (size_t)(bm + arow) * 1024 + k0 + aco);
            int wrow = c >> 4, wco = (c & 15) * 8;
            cp_async16(&sW[buf * W_SZ + wrow * WPAD + wco],
                       Wm + (size_t)(k0 + wrow) * 1024 + bn + wco);
        }
    };

    // prologue: stage tiles 0,1
#pragma unroll
    for (int s = 0; s < STAGES - 1; s++) {
        stage(s, s * 64);
        CP_COMMIT();
    }

    for (int kt = 0; kt < 16; kt++) {
        CP_WAIT(STAGES - 2);       // tile kt landed
        __syncthreads();           // all warps done with tile kt-1 (staging target)

        int nk = kt + STAGES - 1;
        if (nk < 16) stage(nk % STAGES, nk * 64);
        CP_COMMIT();

        const __half* cA = sA + (kt % STAGES) * A_SZ;
        const __half* cW = sW + (kt % STAGES) * W_SZ;

#pragma unroll
        for (int kk = 0; kk < 64; kk += 16) {
            uint32_t a[4][4], b_[2][4];
#pragma unroll
            for (int mt = 0; mt < 4; mt++)
                ldm_x4(a[mt], &cA[(wm + mt * 16 + lrow) * APAD + kk + lcol]);
#pragma unroll
            for (int np = 0; np < 2; np++)
                ldm_x4_t(b_[np], &cW[(kk + lrow) * WPAD + wn + np * 16 + lcol]);
#pragma unroll
            for (int mt = 0; mt < 4; mt++)
#pragma unroll
                for (int nt = 0; nt < 4; nt++)
                    mma16816(acc[mt][nt], a[mt], &b_[nt >> 1][(nt & 1) * 2]);
        }
    }

    const int g = lane >> 2, t4 = lane & 3;
#pragma unroll
    for (int mt = 0; mt < 4; mt++)
#pragma unroll
        for (int nt = 0; nt < 4; nt++) {
            int m0 = bm + wm + mt * 16 + g;
            int n0 = bn + wn + nt * 8 + t4 * 2;
            float b0 = __ldg(bias + n0), b1 = __ldg(bias + n0 + 1);
            store2(C, O, mode, m0,     n0, acc[mt][nt][0] + b0, acc[mt][nt][1] + b1);
            store2(C, O, mode, m0 + 8, n0, acc[mt][nt][2] + b0, acc[mt][nt][3] + b1);
        }
}

// Fused Q/K/V projection: blockIdx.z selects input/weight/bias/output.
__global__ void __launch_bounds__(256) gemm_qkv_kernel(
    const __half* __restrict__ Aq, const __half* __restrict__ Ak,
    const __half* __restrict__ Av, const __half* __restrict__ Wall,
    const float* __restrict__ bq, const float* __restrict__ bk,
    const float* __restrict__ bv,
    __half* __restrict__ Oq, __half* __restrict__ Ok, __half* __restrict__ Ov)
{
    extern __shared__ __half smem[];
    int z = blockIdx.z;
    const __half* A = (z == 0) ? Aq : (z == 1) ? Ak : Av;
    const float* bias = (z == 0) ? bq : (z == 1) ? bk : bv;
    __half* O = (z == 0) ? Oq : (z == 1) ? Ok : Ov;
    gemm_body(A, Wall + (size_t)z * DD * DD, bias, nullptr, O,
              (z == 0) ? 1 : 2, smem);
}

// Output projection (fp32 out).
__global__ void __launch_bounds__(256) gemm_o_kernel(
    const __half* __restrict__ A, const __half* __restrict__ Wm,
    const float* __restrict__ bias, float* __restrict__ C)
{
    extern __shared__ __half smem[];
    gemm_body(A, Wm, bias, C, nullptr, 0, smem);
}

// ---------------------------------------------------------------------------
// Flash-style register-resident sparse attention (unchanged, proven).
// ---------------------------------------------------------------------------
#define KVS 72

__global__ void __launch_bounds__(128) attn_flash_kernel(
    const __half* __restrict__ qg, const __half* __restrict__ kg,
    const __half* __restrict__ vg, __half* __restrict__ out)
{
    __shared__ __half Qs[64 * KVS];
    __shared__ __half Kb[2][64 * KVS];
    __shared__ __half Vb[2][64 * KVS];

    const int tid = threadIdx.x, lane = tid & 31, w = tid >> 5;
    const int qt = 3 - (blockIdx.x >> 8);
    const int bh = (blockIdx.x & 255) >> 2;
    const int r  = blockIdx.x & 3;
    const int q0 = qt * 64;
    const int ntiles = qt + 1;

    const int wq = w * 16;
    const int g = lane >> 2, t4 = lane & 3;
    const int lrow = lane & 15, lcol = (lane >> 4) << 3;
    const int bnrow = ((lane >> 4) << 3) + (lane & 7);
    const int bkoff = ((lane >> 3) & 1) << 3;

    const __half* kbase = kg + (((size_t)bh * 4 + r) * 256) * 64;
    const __half* vbase = vg + (((size_t)bh * 4 + r) * 256) * 64;

#pragma unroll
    for (int j = 0; j < 4; j++) {
        int c = tid + 128 * j, row = c >> 3, co = (c & 7) * 8;
        int i = 4 * (q0 + row) + r;
        *(uint4*)&Qs[row * KVS + co] =
            *(const uint4*)(qg + ((size_t)bh * 1024 + i) * 64 + co);
    }
    __syncthreads();

    auto stage_kv = [&](int buf, int ut) {
#pragma unroll
        for (int j = 0; j < 4; j++) {
            int c = tid + 128 * j, row = c >> 3, co = (c & 7) * 8;
            cp_async16(&Kb[buf][row * KVS + co], kbase + (size_t)(ut * 64 + row) * 64 + co);
            cp_async16(&Vb[buf][row * KVS + co], vbase + (size_t)(ut * 64 + row) * 64 + co);
        }
    };
    stage_kv(0, 0);
    CP_COMMIT();

    uint32_t qf[4][4];
#pragma unroll
    for (int ks = 0; ks < 4; ks++)
        ldm_x4(qf[ks], &Qs[(wq + lrow) * KVS + ks * 16 + lcol]);

    const int i_g  = 4 * (q0 + wq + g) + r;
    const int i_g8 = i_g + 32;
    float m_g, m_g8, l_g, l_g8;
    float oacc[8][4];
#pragma unroll
    for (int nt = 0; nt < 8; nt++)
#pragma unroll
        for (int c = 0; c < 4; c++) oacc[nt][c] = 0.f;
    {
        float sg[3], sg8[3];
        const int nl_g = min(i_g, 3), nl_g8 = min(i_g8, 3);
#pragma unroll
        for (int l = 0; l < 3; l++) {
            float d0 = 0.f, d1 = 0.f;
            int jg = i_g - 1 - l, jg8 = i_g8 - 1 - l;
            if (l < nl_g) {
                const __half* kp = kg + ((((size_t)bh * 4 + (jg & 3)) * 256 + (jg >> 2)) * 64);
#pragma unroll
                for (int d = 0; d < 16; d += 2) {
                    __half2 a = *(const __half2*)&Qs[(wq + g) * KVS + t4 * 16 + d];
                    __half2 b = *(const __half2*)(kp + t4 * 16 + d);
                    d0 += __half2float(a.x) * __half2float(b.x)
                        + __half2float(a.y) * __half2float(b.y);
                }
            }
            if (l < nl_g8) {
                const __half* kp = kg + ((((size_t)bh * 4 + (jg8 & 3)) * 256 + (jg8 >> 2)) * 64);
#pragma unroll
                for (int d = 0; d < 16; d += 2) {
                    __half2 a = *(const __half2*)&Qs[(wq + g + 8) * KVS + t4 * 16 + d];
                    __half2 b = *(const __half2*)(kp + t4 * 16 + d);
                    d1 += __half2float(a.x) * __half2float(b.x)
                        + __half2float(a.y) * __half2float(b.y);
                }
            }
            d0 += __shfl_xor_sync(0xffffffffu, d0, 1);
            d0 += __shfl_xor_sync(0xffffffffu, d0, 2);
            d1 += __shfl_xor_sync(0xffffffffu, d1, 1);
            d1 += __shfl_xor_sync(0xffffffffu, d1, 2);
            sg[l]  = (l < nl_g)  ? d0 * 0.125f : -1e30f;
            sg8[l] = (l < nl_g8) ? d1 * 0.125f : -1e30f;
        }
        m_g  = fmaxf(fmaxf(sg[0], sg[1]), sg[2]);
        m_g8 = fmaxf(fmaxf(sg8[0], sg8[1]), sg8[2]);
        float p_g[3], p_g8[3];
        l_g = 0.f; l_g8 = 0.f;
#pragma unroll
        for (int l = 0; l < 3; l++) {
            p_g[l]  = (l < nl_g)  ? __expf(sg[l] - m_g)   : 0.f;
            p_g8[l] = (l < nl_g8) ? __expf(sg8[l] - m_g8) : 0.f;
            l_g += p_g[l]; l_g8 += p_g8[l];
        }
#pragma unroll
        for (int l = 0; l < 3; l++) {
            int jg = i_g - 1 - l, jg8 = i_g8 - 1 - l;
            if (l < nl_g) {
                const __half* vp = vg + ((((size_t)bh * 4 + (jg & 3)) * 256 + (jg >> 2)) * 64);
#pragma unroll
                for (int nt = 0; nt < 8; nt++) {
                    __half2 v2 = *(const __half2*)(vp + nt * 8 + t4 * 2);
                    oacc[nt][0] += p_g[l] * __half2float(v2.x);
                    oacc[nt][1] += p_g[l] * __half2float(v2.y);
                }
            }
            if (l < nl_g8) {
                const __half* vp = vg + ((((size_t)bh * 4 + (jg8 & 3)) * 256 + (jg8 >> 2)) * 64);
#pragma unroll
                for (int nt = 0; nt < 8; nt++) {
                    __half2 v2 = *(const __half2*)(vp + nt * 8 + t4 * 2);
                    oacc[nt][2] += p_g8[l] * __half2float(v2.x);
                    oacc[nt][3] += p_g8[l] * __half2float(v2.y);
                }
            }
        }
    }

    int buf = 0;
    for (int ut = 0; ut < ntiles; ut++) {
        CP_WAIT(0);
        __syncthreads();
        if (ut + 1 < ntiles) {
            stage_kv(buf ^ 1, ut + 1);
            CP_COMMIT();
        }

        float acc[8][4];
#pragma unroll
        for (int nt = 0; nt < 8; nt++)
#pragma unroll
            for (int c = 0; c < 4; c++) acc[nt][c] = 0.f;
#pragma unroll
        for (int ks = 0; ks < 4; ks++)
#pragma unroll
            for (int nb = 0; nb < 4; nb++) {
                uint32_t bh4[4];
                ldm_x4(bh4, &Kb[buf][(nb * 16 + bnrow) * KVS + ks * 16 + bkoff]);
                mma16816(acc[nb * 2 + 0], qf[ks], &bh4[0]);
                mma16816(acc[nb * 2 + 1], qf[ks], &bh4[2]);
            }

        if (ut == qt) {
            const int lim_g = wq + g, lim_g8 = wq + g + 8;
#pragma unroll
            for (int nt = 0; nt < 8; nt++) {
                int u0 = nt * 8 + t4 * 2;
                acc[nt][0] = (u0     <= lim_g)  ? acc[nt][0] * 0.125f : -1e30f;
                acc[nt][1] = (u0 + 1 <= lim_g)  ? acc[nt][1] * 0.125f : -1e30f;
                acc[nt][2] = (u0     <= lim_g8) ? acc[nt][2] * 0.125f : -1e30f;
                acc[nt][3] = (u0 + 1 <= lim_g8) ? acc[nt][3] * 0.125f : -1e30f;
            }
        } else {
#pragma unroll
            for (int nt = 0; nt < 8; nt++)
#pragma unroll
                for (int c = 0; c < 4; c++) acc[nt][c] *= 0.125f;
        }

        float tm_g = -1e30f, tm_g8 = -1e30f;
#pragma unroll
        for (int nt = 0; nt < 8; nt++) {
            tm_g  = fmaxf(tm_g,  fmaxf(acc[nt][0], acc[nt][1]));
            tm_g8 = fmaxf(tm_g8, fmaxf(acc[nt][2], acc[nt][3]));
        }
        tm_g  = fmaxf(tm_g,  __shfl_xor_sync(0xffffffffu, tm_g, 1));
        tm_g  = fmaxf(tm_g,  __shfl_xor_sync(0xffffffffu, tm_g, 2));
        tm_g8 = fmaxf(tm_g8, __shfl_xor_sync(0xffffffffu, tm_g8, 1));
        tm_g8 = fmaxf(tm_g8, __shfl_xor_sync(0xffffffffu, tm_g8, 2));

        float mn_g = fmaxf(m_g, tm_g), mn_g8 = fmaxf(m_g8, tm_g8);
        float al_g = __expf(m_g - mn_g), al_g8 = __expf(m_g8 - mn_g8);
        m_g = mn_g; m_g8 = mn_g8;

        float ps_g = 0.f, ps_g8 = 0.f;
#pragma unroll
        for (int nt = 0; nt < 8; nt++) {
            float p0 = __expf(acc[nt][0] - mn_g);
            float p1 = __expf(acc[nt][1] - mn_g);
            float p2 = __expf(acc[nt][2] - mn_g8);
            float p3 = __expf(acc[nt][3] - mn_g8);
            acc[nt][0] = p0; acc[nt][1] = p1; acc[nt][2] = p2; acc[nt][3] = p3;
            ps_g += p0 + p1; ps_g8 += p2 + p3;
        }
        ps_g  += __shfl_xor_sync(0xffffffffu, ps_g, 1);
        ps_g  += __shfl_xor_sync(0xffffffffu, ps_g, 2);
        ps_g8 += __shfl_xor_sync(0xffffffffu, ps_g8, 1);
        ps_g8 += __shfl_xor_sync(0xffffffffu, ps_g8, 2);
        l_g = l_g * al_g + ps_g;
        l_g8 = l_g8 * al_g8 + ps_g8;
#pragma unroll
        for (int nt = 0; nt < 8; nt++) {
            oacc[nt][0] *= al_g;  oacc[nt][1] *= al_g;
            oacc[nt][2] *= al_g8; oacc[nt][3] *= al_g8;
        }

#pragma unroll
        for (int ks = 0; ks < 4; ks++) {
            uint32_t pa[4];
            pa[0] = packh2(acc[2 * ks][0],     acc[2 * ks][1]);
            pa[1] = packh2(acc[2 * ks][2],     acc[2 * ks][3]);
            pa[2] = packh2(acc[2 * ks + 1][0], acc[2 * ks + 1][1]);
            pa[3] = packh2(acc[2 * ks + 1][2], acc[2 * ks + 1][3]);
#pragma unroll
            for (int nb = 0; nb < 4; nb++) {
                uint32_t vh4[4];
                ldm_x4_t(vh4, &Vb[buf][(ks * 16 + lrow) * KVS + nb * 16 + lcol]);
                mma16816(oacc[nb * 2 + 0], pa, &vh4[0]);
                mma16816(oacc[nb * 2 + 1], pa, &vh4[2]);
            }
        }
        buf ^= 1;
    }

    __syncthreads();
    {
        float inv_g = 1.0f / l_g, inv_g8 = 1.0f / l_g8;
#pragma unroll
        for (int nt = 0; nt < 8; nt++) {
            *(__half2*)&Qs[(wq + g) * KVS + nt * 8 + t4 * 2] =
                __floats2half2_rn(oacc[nt][0] * inv_g, oacc[nt][1] * inv_g);
            *(__half2*)&Qs[(wq + g + 8) * KVS + nt * 8 + t4 * 2] =
                __floats2half2_rn(oacc[nt][2] * inv_g8, oacc[nt][3] * inv_g8);
        }
    }
    __syncthreads();
    {
        int bb = bh >> 4, h = bh & 15;
#pragma unroll
        for (int j = 0; j < 4; j++) {
            int c = tid + 128 * j, row = c >> 3, co = (c & 7) * 8;
            int i = 4 * (q0 + row) + r;
            *(uint4*)(out + ((size_t)(bb * 1024 + i)) * 1024 + h * 64 + co) =
                *(const uint4*)&Qs[row * KVS + co];
        }
    }
}

// ---------------------------------------------------------------------------
extern "C" void kernel_launch(void* const* d_in, const int* in_sizes, int n_in,
                              void* d_out, int out_size)
{
    const float* Q  = (const float*)d_in[0];
    const float* K  = (const float*)d_in[1];
    const float* V  = (const float*)d_in[2];
    const float* Wq = (const float*)d_in[3];
    const float* bq = (const float*)d_in[4];
    const float* Wk = (const float*)d_in[5];
    const float* bk = (const float*)d_in[6];
    const float* Wv = (const float*)d_in[7];
    const float* bv = (const float*)d_in[8];
    const float* Wo = (const float*)d_in[9];
    const float* bo = (const float*)d_in[10];
    float* out = (float*)d_out;

    __half *pqin, *pkin, *pvin, *pw, *pq, *pk, *pv, *pah;
    cudaGetSymbolAddress((void**)&pqin, g_qin);
    cudaGetSymbolAddress((void**)&pkin, g_kin);
    cudaGetSymbolAddress((void**)&pvin, g_vin);
    cudaGetSymbolAddress((void**)&pw, g_w);
    cudaGetSymbolAddress((void**)&pq, g_q);
    cudaGetSymbolAddress((void**)&pk, g_k);
    cudaGetSymbolAddress((void**)&pv, g_v);
    cudaGetSymbolAddress((void**)&pah, g_attn);

    cudaFuncSetAttribute(gemm_qkv_kernel,
                         cudaFuncAttributeMaxDynamicSharedMemorySize, GEMM_SMEM);
    cudaFuncSetAttribute(gemm_o_kernel,
                         cudaFuncAttributeMaxDynamicSharedMemorySize, GEMM_SMEM);

    convall_kernel<<<16384, 256>>>(Q, K, V, Wq, Wk, Wv, Wo, pqin, pkin, pvin, pw);

    gemm_qkv_kernel<<<dim3(8, 32, 3), 256, GEMM_SMEM>>>(
        pqin, pkin, pvin, pw, bq, bk, bv, pq, pk, pv);

    attn_flash_kernel<<<1024, 128>>>(pq, pk, pv, pah);

    gemm_o_kernel<<<dim3(8, 32), 256, GEMM_SMEM>>>(
        pah, pw + 3 * (size_t)DD * DD, bo, out);
}